// round 1
// baseline (speedup 1.0000x reference)
#include <cuda_runtime.h>
#include <math.h>

#define I_ 64
#define R_ 36
#define D_ 1024
#define C_ 64
#define W_ 32
#define N_ (I_*R_)       // 2304
#define MROWS (C_*W_)    // 2048
#define SMOOTH_ 9.0f
#define EPS_ 1e-8f
#define MASK_VAL_ (-1.0f)

// ---- static scratch (no allocation allowed) ----
__device__ float d_S[MROWS * N_];          // raw logits S[w_act][i*36+r], ~18.9MB
__device__ float d_G[I_ * R_ * R_];        // per-image Gram matrices
__device__ float d_capn[C_ * W_];          // ||caps[c,w]||^2
__device__ int   d_rowmap[MROWS];          // active row -> c*32+w
__device__ int   d_actoff[C_];             // per-c offset into active rows
__device__ int   d_act_total;

// ============================================================
// 0) compaction of active (c,w) rows
// ============================================================
__global__ void prep_kernel(const int* __restrict__ cap_lens) {
    __shared__ int offs[C_ + 1];
    int tid = threadIdx.x;
    if (tid == 0) {
        int run = 0;
        for (int c = 0; c < C_; c++) { offs[c] = run; run += cap_lens[c]; }
        offs[C_] = run;
        d_act_total = run;
    }
    __syncthreads();
    int c = tid;                       // blockDim == 64
    int off = offs[c], nw = cap_lens[c];
    d_actoff[c] = off;
    for (int w = 0; w < nw; w++) d_rowmap[off + w] = c * W_ + w;
    int total = offs[C_];
    for (int idx = total + tid; idx < MROWS; idx += C_) d_rowmap[idx] = 0;
}

// ============================================================
// 1) caption row norms:  capn[c][w] = sum_d caps^2
// ============================================================
__global__ void capn_kernel(const float* __restrict__ caps) {
    int c = blockIdx.x;
    int tid = threadIdx.x;             // 256
    int w = tid >> 3, l = tid & 7;
    const float* p = caps + ((size_t)(c * W_ + w)) * D_;
    float s = 0.f;
    for (int d = l; d < D_; d += 8) { float v = p[d]; s += v * v; }
    s += __shfl_down_sync(0xffffffffu, s, 4);
    s += __shfl_down_sync(0xffffffffu, s, 2);
    s += __shfl_down_sync(0xffffffffu, s, 1);
    if (l == 0) d_capn[c * W_ + w] = s;
}

// ============================================================
// 2) Gram matrices: G[i][r][r'] = imgs[i,r,:] . imgs[i,r',:]
//    one CTA per i; 12x12 thread grid, 3x3 register tiles
// ============================================================
__global__ void gram_kernel(const float* __restrict__ imgs) {
    __shared__ float sm[R_][129];      // 128-wide d-chunk, +1 pad
    int i = blockIdx.x, tid = threadIdx.x;   // 256 threads
    int tr = tid / 12, tc = tid % 12;
    float acc[3][3] = {};
    const float* base = imgs + (size_t)i * R_ * D_;
    for (int d0 = 0; d0 < D_; d0 += 128) {
        for (int idx = tid; idx < R_ * 128; idx += 256) {
            int r = idx >> 7, d = idx & 127;
            sm[r][d] = base[r * D_ + d0 + d];
        }
        __syncthreads();
        if (tid < 144) {
            #pragma unroll 4
            for (int d = 0; d < 128; d++) {
                float a0 = sm[tr*3+0][d], a1 = sm[tr*3+1][d], a2 = sm[tr*3+2][d];
                float b0 = sm[tc*3+0][d], b1 = sm[tc*3+1][d], b2 = sm[tc*3+2][d];
                acc[0][0] = fmaf(a0,b0,acc[0][0]); acc[0][1] = fmaf(a0,b1,acc[0][1]); acc[0][2] = fmaf(a0,b2,acc[0][2]);
                acc[1][0] = fmaf(a1,b0,acc[1][0]); acc[1][1] = fmaf(a1,b1,acc[1][1]); acc[1][2] = fmaf(a1,b2,acc[1][2]);
                acc[2][0] = fmaf(a2,b0,acc[2][0]); acc[2][1] = fmaf(a2,b1,acc[2][1]); acc[2][2] = fmaf(a2,b2,acc[2][2]);
            }
        }
        __syncthreads();
    }
    if (tid < 144) {
        #pragma unroll
        for (int a = 0; a < 3; a++)
            #pragma unroll
            for (int b = 0; b < 3; b++)
                d_G[i * R_ * R_ + (tr*3+a) * R_ + (tc*3+b)] = acc[a][b];
    }
}

// ============================================================
// 3) gathered GEMM:  S[m][n] = caps[rowmap[m],:] . imgs_flat[n,:]
//    M = act_total (<=2048), N = 2304, K = 1024
//    BM=64 BN=128 BK=32, 256 threads, 4x8 register tile
// ============================================================
#define BM 64
#define BN 128
#define BK 32
__global__ void __launch_bounds__(256) gemm_kernel(const float* __restrict__ caps,
                                                   const float* __restrict__ imgs) {
    __shared__ float As[BK][BM + 1];   // [32][65]: stride%32==1 -> conflict-free
    __shared__ float Bs[BK][BN + 1];   // [32][129]
    int act_total = d_act_total;
    int m0 = blockIdx.y * BM;
    if (m0 >= act_total) return;       // keep masking savings
    int n0 = blockIdx.x * BN;
    int tid = threadIdx.x;
    int tx = tid & 15, ty = tid >> 4;

    // hoist gather indices for the A loads
    int srcrow[2];
    #pragma unroll
    for (int it = 0; it < 2; it++) {
        int f = tid + it * 256;
        srcrow[it] = d_rowmap[m0 + (f >> 3)];
    }

    float acc[4][8] = {};
    for (int k0 = 0; k0 < D_; k0 += BK) {
        #pragma unroll
        for (int it = 0; it < 2; it++) {
            int f = tid + it * 256;
            int row = f >> 3, kc = f & 7;
            float4 v = *reinterpret_cast<const float4*>(&caps[(size_t)srcrow[it] * D_ + k0 + kc*4]);
            As[kc*4+0][row] = v.x; As[kc*4+1][row] = v.y;
            As[kc*4+2][row] = v.z; As[kc*4+3][row] = v.w;
        }
        #pragma unroll
        for (int it = 0; it < 4; it++) {
            int f = tid + it * 256;
            int nr = f >> 3, kc = f & 7;
            float4 v = *reinterpret_cast<const float4*>(&imgs[(size_t)(n0 + nr) * D_ + k0 + kc*4]);
            Bs[kc*4+0][nr] = v.x; Bs[kc*4+1][nr] = v.y;
            Bs[kc*4+2][nr] = v.z; Bs[kc*4+3][nr] = v.w;
        }
        __syncthreads();
        #pragma unroll
        for (int kk = 0; kk < BK; kk++) {
            float a[4], b[8];
            #pragma unroll
            for (int ii = 0; ii < 4; ii++) a[ii] = As[kk][ty + 16*ii];
            #pragma unroll
            for (int jj = 0; jj < 8; jj++) b[jj] = Bs[kk][tx + 16*jj];
            #pragma unroll
            for (int ii = 0; ii < 4; ii++)
                #pragma unroll
                for (int jj = 0; jj < 8; jj++)
                    acc[ii][jj] = fmaf(a[ii], b[jj], acc[ii][jj]);
        }
        __syncthreads();
    }
    #pragma unroll
    for (int ii = 0; ii < 4; ii++) {
        int m = m0 + ty + 16*ii;
        if (m < act_total) {
            #pragma unroll
            for (int jj = 0; jj < 8; jj++)
                d_S[(size_t)m * N_ + n0 + tx + 16*jj] = acc[ii][jj];
        }
    }
}

// ============================================================
// 4) epilogue per (c,i): leaky-relu, w-norm, softmax over r,
//    then sim via Gram quadratic form + bilinear dot.
// ============================================================
__global__ void __launch_bounds__(128) post_kernel(const int* __restrict__ cap_lens,
                                                   float* __restrict__ out) {
    int i = blockIdx.x, c = blockIdx.y;
    int tid = threadIdx.x;
    int lane = tid & 31, wid = tid >> 5;
    int nw = cap_lens[c], m0 = d_actoff[c];

    __shared__ float Ss[W_][37];
    __shared__ float Gs[R_][37];
    __shared__ float cn[R_];

    if (tid < W_ && tid >= nw)
        out[((size_t)i * C_ + c) * W_ + tid] = MASK_VAL_;

    for (int idx = tid; idx < R_ * R_; idx += 128)
        Gs[idx / R_][idx % R_] = d_G[i * R_ * R_ + idx];
    for (int idx = tid; idx < nw * R_; idx += 128) {
        int w = idx / R_, r = idx - w * R_;
        Ss[w][r] = d_S[(size_t)(m0 + w) * N_ + i * R_ + r];
    }
    __syncthreads();

    if (tid < R_) {
        float s = 0.f;
        for (int w = 0; w < nw; w++) {
            float v = Ss[w][tid];
            v = (v >= 0.f) ? v : 0.1f * v;
            s += v * v;
        }
        cn[tid] = sqrtf(s) + EPS_;
    }
    __syncthreads();

    for (int w = wid; w < nw; w += 4) {
        float s0 = Ss[w][lane];
        float s1 = (lane < 4) ? Ss[w][32 + lane] : 0.f;
        float l0 = (s0 >= 0.f) ? s0 : 0.1f * s0;
        float l1 = (s1 >= 0.f) ? s1 : 0.1f * s1;
        float a0 = l0 / cn[lane] * SMOOTH_;
        float a1 = (lane < 4) ? (l1 / cn[32 + lane] * SMOOTH_) : -1e30f;

        float mx = fmaxf(a0, a1);
        #pragma unroll
        for (int o = 16; o; o >>= 1) mx = fmaxf(mx, __shfl_xor_sync(~0u, mx, o));
        float e0 = expf(a0 - mx);
        float e1 = (lane < 4) ? expf(a1 - mx) : 0.f;
        float sum = e0 + e1;
        #pragma unroll
        for (int o = 16; o; o >>= 1) sum += __shfl_xor_sync(~0u, sum, o);
        float p0 = e0 / sum, p1 = e1 / sum;

        // cap.wctx = sum_r p_r * S_raw[w][r]
        float dot = p0 * s0 + p1 * s1;
        #pragma unroll
        for (int o = 16; o; o >>= 1) dot += __shfl_xor_sync(~0u, dot, o);

        // ||wctx||^2 = p^T G p
        float y0 = 0.f, y1 = 0.f;
        #pragma unroll 4
        for (int rp = 0; rp < R_; rp++) {
            float pv = (rp < 32) ? __shfl_sync(~0u, p0, rp)
                                 : __shfl_sync(~0u, p1, rp - 32);
            y0 = fmaf(Gs[lane][rp], pv, y0);
            if (lane < 4) y1 = fmaf(Gs[32 + lane][rp], pv, y1);
        }
        float q = p0 * y0 + p1 * y1;
        #pragma unroll
        for (int o = 16; o; o >>= 1) q += __shfl_xor_sync(~0u, q, o);

        if (lane == 0) {
            float n = sqrtf(q);
            float denom = n + EPS_;
            float w12 = dot / denom;
            float w2v = n / denom;
            float w1v = sqrtf(d_capn[c * W_ + w]);
            float sim = w12 / fmaxf(w1v * w2v, EPS_);
            out[((size_t)i * C_ + c) * W_ + w] = sim;
        }
    }
}

// ============================================================
extern "C" void kernel_launch(void* const* d_in, const int* in_sizes, int n_in,
                              void* d_out, int out_size) {
    const float* imgs     = (const float*)d_in[0];
    const float* caps     = (const float*)d_in[1];
    // d_in[2] = img_lens (unused by the reference)
    const int*   cap_lens = (const int*)d_in[3];
    float* out = (float*)d_out;

    prep_kernel<<<1, C_>>>(cap_lens);
    capn_kernel<<<C_, 256>>>(caps);
    gram_kernel<<<I_, 256>>>(imgs);
    dim3 ggrid(N_ / BN, MROWS / BM);   // (18, 32)
    gemm_kernel<<<ggrid, 256>>>(caps, imgs);
    dim3 pgrid(I_, C_);
    post_kernel<<<pgrid, 128>>>(cap_lens, out);
}

// round 4
// speedup vs baseline: 1.8442x; 1.8442x over previous
#include <cuda_runtime.h>
#include <cuda_bf16.h>
#include <cstdint>
#include <math.h>

#define I_ 64
#define R_ 36
#define D_ 1024
#define C_ 64
#define W_ 32
#define N_ (I_*R_)       // 2304
#define MROWS (C_*W_)    // 2048
#define SMOOTH_ 9.0f
#define EPS_ 1e-8f
#define MASK_VAL_ (-1.0f)

// GEMM tiling
#define BM 128
#define BN 128
#define BK 32                    // bf16 k-elems per stage
#define NSTAGE (D_/BK)           // 32
#define ROWB 80                  // smem row stride bytes (5*16B: ldmatrix conflict-free)
#define TILEB (BM*ROWB)          // 10240 B per operand tile
#define GEMM_SMEM (2*4*TILEB)    // 81920 (2 stages x {Ah,Al,Bh,Bl})

// ---- static scratch ----
__device__ float d_S[MROWS * N_];          // raw logits, ~18.9MB
__device__ float d_G[I_ * R_ * R_];
__device__ float d_capn[C_ * W_];
__device__ int   d_rowmap[MROWS];
__device__ int   d_actoff[C_];
__device__ int   d_act_total;

// row-major gathered bf16 hi/lo operands
__device__ __nv_bfloat16 d_Ath[MROWS * D_];   // 4MB
__device__ __nv_bfloat16 d_Atl[MROWS * D_];
__device__ __nv_bfloat16 d_Bth[N_ * D_];      // 4.5MB
__device__ __nv_bfloat16 d_Btl[N_ * D_];

// ================= PTX helpers (all baseline sm_80+/sm_90, no 'a' features) ====
__device__ __forceinline__ uint32_t smem_u32(const void* p) {
    uint32_t a;
    asm("{ .reg .u64 t; cvta.to.shared.u64 t, %1; cvt.u32.u64 %0, t; }" : "=r"(a) : "l"(p));
    return a;
}
__device__ __forceinline__ void cpasync16(uint32_t dst, const void* src) {
    asm volatile("cp.async.cg.shared.global [%0], [%1], 16;" :: "r"(dst), "l"(src) : "memory");
}
#define CP_COMMIT() asm volatile("cp.async.commit_group;" ::: "memory")
#define CP_WAIT(n)  asm volatile("cp.async.wait_group %0;" :: "n"(n) : "memory")

__device__ __forceinline__ void ldsm4(uint32_t r[4], uint32_t addr) {
    asm volatile("ldmatrix.sync.aligned.m8n8.x4.shared.b16 {%0,%1,%2,%3}, [%4];"
                 : "=r"(r[0]), "=r"(r[1]), "=r"(r[2]), "=r"(r[3]) : "r"(addr));
}
__device__ __forceinline__ void mma16816(float* d, const uint32_t* a, const uint32_t* b0, const uint32_t* b1) {
    asm volatile("mma.sync.aligned.m16n8k16.row.col.f32.bf16.bf16.f32 "
                 "{%0,%1,%2,%3},{%4,%5,%6,%7},{%8,%9},{%0,%1,%2,%3};"
                 : "+f"(d[0]), "+f"(d[1]), "+f"(d[2]), "+f"(d[3])
                 : "r"(a[0]), "r"(a[1]), "r"(a[2]), "r"(a[3]), "r"(*b0), "r"(*b1));
}

// ============================================================
// 0) compaction of active (c,w) rows
// ============================================================
__global__ void prep_kernel(const int* __restrict__ cap_lens) {
    __shared__ int offs[C_ + 1];
    int tid = threadIdx.x;
    if (tid == 0) {
        int run = 0;
        for (int c = 0; c < C_; c++) { offs[c] = run; run += cap_lens[c]; }
        offs[C_] = run;
        d_act_total = run;
    }
    __syncthreads();
    int c = tid;
    int off = offs[c], nw = cap_lens[c];
    d_actoff[c] = off;
    for (int w = 0; w < nw; w++) d_rowmap[off + w] = c * W_ + w;
    int total = offs[C_];
    for (int idx = total + tid; idx < MROWS; idx += C_) d_rowmap[idx] = 0;
}

// ============================================================
// 1) caption row norms
// ============================================================
__global__ void capn_kernel(const float* __restrict__ caps) {
    int c = blockIdx.x;
    int tid = threadIdx.x;
    int w = tid >> 3, l = tid & 7;
    const float* p = caps + ((size_t)(c * W_ + w)) * D_;
    float s = 0.f;
    for (int d = l; d < D_; d += 8) { float v = p[d]; s += v * v; }
    s += __shfl_down_sync(0xffffffffu, s, 4);
    s += __shfl_down_sync(0xffffffffu, s, 2);
    s += __shfl_down_sync(0xffffffffu, s, 1);
    if (l == 0) d_capn[c * W_ + w] = s;
}

// ============================================================
// 2) convert: fp32 -> bf16 hi/lo, row-major (A gathered via rowmap)
//    one 8-elem chunk per thread
// ============================================================
#define ACH (MROWS * (D_/8))   // 262144
#define BCH (N_ * (D_/8))      // 294912
__global__ void convert_kernel(const float* __restrict__ caps, const float* __restrict__ imgs) {
    int t = blockIdx.x * 256 + threadIdx.x;
    const float* src;
    size_t dsto;
    __nv_bfloat16 *bh, *bl;
    if (t < ACH) {
        int row = t >> 7, c8 = t & 127;
        src = caps + (size_t)d_rowmap[row] * D_ + c8 * 8;
        dsto = (size_t)row * D_ + c8 * 8;
        bh = d_Ath; bl = d_Atl;
    } else if (t < ACH + BCH) {
        int u = t - ACH;
        int row = u >> 7, c8 = u & 127;
        src = imgs + (size_t)row * D_ + c8 * 8;
        dsto = (size_t)row * D_ + c8 * 8;
        bh = d_Bth; bl = d_Btl;
    } else return;

    float4 v0 = *reinterpret_cast<const float4*>(src);
    float4 v1 = *reinterpret_cast<const float4*>(src + 4);
    float v[8] = {v0.x, v0.y, v0.z, v0.w, v1.x, v1.y, v1.z, v1.w};
    union { __nv_bfloat16 h[8]; uint4 u; } Hi, Lo;
    #pragma unroll
    for (int k = 0; k < 8; k++) {
        __nv_bfloat16 hb = __float2bfloat16(v[k]);
        float r = v[k] - __bfloat162float(hb);
        Hi.h[k] = hb;
        Lo.h[k] = __float2bfloat16(r);
    }
    *reinterpret_cast<uint4*>(bh + dsto) = Hi.u;
    *reinterpret_cast<uint4*>(bl + dsto) = Lo.u;
}

// ============================================================
// 3) Gram matrices
// ============================================================
__global__ void gram_kernel(const float* __restrict__ imgs) {
    __shared__ float sm[R_][129];
    int i = blockIdx.x, tid = threadIdx.x;
    int tr = tid / 12, tc = tid % 12;
    float acc[3][3] = {};
    const float* base = imgs + (size_t)i * R_ * D_;
    for (int d0 = 0; d0 < D_; d0 += 128) {
        for (int idx = tid; idx < R_ * 128; idx += 256) {
            int r = idx >> 7, d = idx & 127;
            sm[r][d] = base[r * D_ + d0 + d];
        }
        __syncthreads();
        if (tid < 144) {
            #pragma unroll 4
            for (int d = 0; d < 128; d++) {
                float a0 = sm[tr*3+0][d], a1 = sm[tr*3+1][d], a2 = sm[tr*3+2][d];
                float b0 = sm[tc*3+0][d], b1 = sm[tc*3+1][d], b2 = sm[tc*3+2][d];
                acc[0][0] = fmaf(a0,b0,acc[0][0]); acc[0][1] = fmaf(a0,b1,acc[0][1]); acc[0][2] = fmaf(a0,b2,acc[0][2]);
                acc[1][0] = fmaf(a1,b0,acc[1][0]); acc[1][1] = fmaf(a1,b1,acc[1][1]); acc[1][2] = fmaf(a1,b2,acc[1][2]);
                acc[2][0] = fmaf(a2,b0,acc[2][0]); acc[2][1] = fmaf(a2,b1,acc[2][1]); acc[2][2] = fmaf(a2,b2,acc[2][2]);
            }
        }
        __syncthreads();
    }
    if (tid < 144) {
        #pragma unroll
        for (int a = 0; a < 3; a++)
            #pragma unroll
            for (int b = 0; b < 3; b++)
                d_G[i * R_ * R_ + (tr*3+a) * R_ + (tc*3+b)] = acc[a][b];
    }
}

// ============================================================
// 4) HMMA bf16x3 GEMM: S = A_gathered . B^T  (fp32-accurate via hi/lo split)
//    2-stage cp.async pipeline, ldmatrix, m16n8k16
// ============================================================
__global__ void __launch_bounds__(256, 1) gemm_mma_kernel() {
    extern __shared__ __align__(128) char smc[];
    uint32_t sb = smem_u32(smc);
    int tid = threadIdx.x, wid = tid >> 5, lane = tid & 31;

    int act = d_act_total;
    int mblk = blockIdx.y;
    if (mblk * BM >= act) return;
    int nblk = blockIdx.x;

    // warp layout: wr in {0,1} -> 64-row half, wc in {0..3} -> 32-col quarter
    int wr = wid & 1, wc = wid >> 1;

    const __nv_bfloat16* srcs[4] = {
        d_Ath + (size_t)mblk * BM * D_,
        d_Atl + (size_t)mblk * BM * D_,
        d_Bth + (size_t)nblk * BN * D_,
        d_Btl + (size_t)nblk * BN * D_
    };

    // ldmatrix per-thread addressing: q = lane>>3 selects 8x8 sub-matrix
    int q = lane >> 3, lr = lane & 7;
    int rowoff = ((q & 1) << 3) + lr;    // 0..15 within 16-row tile
    int csel = q >> 1;                   // 0/1: which 16B k-chunk of the k16
    uint32_t aoff = (uint32_t)((wr * 64 + rowoff) * ROWB + csel * 16);
    uint32_t boff = (uint32_t)((wc * 32 + rowoff) * ROWB + csel * 16);

    float acc[4][4][4] = {};

    // ---- load one stage: 4 tiles x 512 chunks(16B), 8 chunks/thread ----
    #define LOAD_STAGE(s, k0) do {                                              \
        _Pragma("unroll")                                                        \
        for (int it = 0; it < 8; it++) {                                         \
            int ci = tid + it * 256;                                             \
            int tt = ci >> 9, r2 = ci & 511;                                     \
            int row = r2 >> 2, cc = r2 & 3;                                      \
            const char* g = (const char*)(srcs[tt] + (size_t)row * D_ + (k0)) + cc * 16; \
            uint32_t dd = sb + (uint32_t)(((s) * 4 + tt) * TILEB + row * ROWB + cc * 16); \
            cpasync16(dd, g);                                                    \
        }                                                                        \
        CP_COMMIT();                                                             \
    } while (0)

    LOAD_STAGE(0, 0);

    for (int ks = 0; ks < NSTAGE; ks++) {
        int s = ks & 1;
        if (ks + 1 < NSTAGE) { LOAD_STAGE(s ^ 1, (ks + 1) * BK); CP_WAIT(1); }
        else                 { CP_WAIT(0); }
        __syncthreads();

        uint32_t bAh = sb + (uint32_t)((s * 4 + 0) * TILEB);
        uint32_t bAl = sb + (uint32_t)((s * 4 + 1) * TILEB);
        uint32_t bBh = sb + (uint32_t)((s * 4 + 2) * TILEB);
        uint32_t bBl = sb + (uint32_t)((s * 4 + 3) * TILEB);

        #pragma unroll
        for (int k16 = 0; k16 < 2; k16++) {
            uint32_t kb = (uint32_t)(k16 * 32);   // 2 chunks of 16B per k16
            uint32_t ah[4][4], al[4][4];
            uint32_t bhf[4][2], blf[4][2];
            #pragma unroll
            for (int mt = 0; mt < 4; mt++) {
                ldsm4(ah[mt], bAh + (uint32_t)(mt * 16 * ROWB) + kb + aoff);
                ldsm4(al[mt], bAl + (uint32_t)(mt * 16 * ROWB) + kb + aoff);
            }
            #pragma unroll
            for (int np = 0; np < 2; np++) {
                uint32_t t4[4];
                ldsm4(t4, bBh + (uint32_t)(np * 16 * ROWB) + kb + boff);
                bhf[np*2+0][0] = t4[0]; bhf[np*2+0][1] = t4[2];
                bhf[np*2+1][0] = t4[1]; bhf[np*2+1][1] = t4[3];
                ldsm4(t4, bBl + (uint32_t)(np * 16 * ROWB) + kb + boff);
                blf[np*2+0][0] = t4[0]; blf[np*2+0][1] = t4[2];
                blf[np*2+1][0] = t4[1]; blf[np*2+1][1] = t4[3];
            }
            #pragma unroll
            for (int mt = 0; mt < 4; mt++)
                #pragma unroll
                for (int nt = 0; nt < 4; nt++) {
                    mma16816(acc[mt][nt], ah[mt], &bhf[nt][0], &bhf[nt][1]);
                    mma16816(acc[mt][nt], ah[mt], &blf[nt][0], &blf[nt][1]);
                    mma16816(acc[mt][nt], al[mt], &bhf[nt][0], &bhf[nt][1]);
                }
        }
        __syncthreads();
    }

    // ---- store: D frag mapping: c0,c1=(g,2t),(g,2t+1); c2,c3=(g+8, ...)
    int g = lane >> 2, tq = lane & 3;
    #pragma unroll
    for (int mt = 0; mt < 4; mt++) {
        int m0 = mblk * BM + wr * 64 + mt * 16 + g;
        #pragma unroll
        for (int nt = 0; nt < 4; nt++) {
            int n = nblk * BN + wc * 32 + nt * 8 + tq * 2;
            if (m0 < act)
                *reinterpret_cast<float2*>(d_S + (size_t)m0 * N_ + n) =
                    make_float2(acc[mt][nt][0], acc[mt][nt][1]);
            if (m0 + 8 < act)
                *reinterpret_cast<float2*>(d_S + (size_t)(m0 + 8) * N_ + n) =
                    make_float2(acc[mt][nt][2], acc[mt][nt][3]);
        }
    }
}

// ============================================================
// 5) epilogue per (c,i)
// ============================================================
__global__ void __launch_bounds__(128) post_kernel(const int* __restrict__ cap_lens,
                                                   float* __restrict__ out) {
    int i = blockIdx.x, c = blockIdx.y;
    int tid = threadIdx.x;
    int lane = tid & 31, wid = tid >> 5;
    int nw = cap_lens[c], m0 = d_actoff[c];

    __shared__ float Ss[W_][37];
    __shared__ float Gs[R_][37];
    __shared__ float cn[R_];

    if (tid < W_ && tid >= nw)
        out[((size_t)i * C_ + c) * W_ + tid] = MASK_VAL_;

    for (int idx = tid; idx < R_ * R_; idx += 128)
        Gs[idx / R_][idx % R_] = d_G[i * R_ * R_ + idx];
    for (int idx = tid; idx < nw * R_; idx += 128) {
        int w = idx / R_, r = idx - w * R_;
        Ss[w][r] = d_S[(size_t)(m0 + w) * N_ + i * R_ + r];
    }
    __syncthreads();

    if (tid < R_) {
        float s = 0.f;
        for (int w = 0; w < nw; w++) {
            float v = Ss[w][tid];
            v = (v >= 0.f) ? v : 0.1f * v;
            s += v * v;
        }
        cn[tid] = sqrtf(s) + EPS_;
    }
    __syncthreads();

    for (int w = wid; w < nw; w += 4) {
        float s0 = Ss[w][lane];
        float s1 = (lane < 4) ? Ss[w][32 + lane] : 0.f;
        float l0 = (s0 >= 0.f) ? s0 : 0.1f * s0;
        float l1 = (s1 >= 0.f) ? s1 : 0.1f * s1;
        float a0 = l0 / cn[lane] * SMOOTH_;
        float a1 = (lane < 4) ? (l1 / cn[32 + lane] * SMOOTH_) : -1e30f;

        float mx = fmaxf(a0, a1);
        #pragma unroll
        for (int o = 16; o; o >>= 1) mx = fmaxf(mx, __shfl_xor_sync(~0u, mx, o));
        float e0 = expf(a0 - mx);
        float e1 = (lane < 4) ? expf(a1 - mx) : 0.f;
        float sum = e0 + e1;
        #pragma unroll
        for (int o = 16; o; o >>= 1) sum += __shfl_xor_sync(~0u, sum, o);
        float p0 = e0 / sum, p1 = e1 / sum;

        float dot = p0 * s0 + p1 * s1;
        #pragma unroll
        for (int o = 16; o; o >>= 1) dot += __shfl_xor_sync(~0u, dot, o);

        float y0 = 0.f, y1 = 0.f;
        #pragma unroll 4
        for (int rp = 0; rp < R_; rp++) {
            float pv = (rp < 32) ? __shfl_sync(~0u, p0, rp)
                                 : __shfl_sync(~0u, p1, rp - 32);
            y0 = fmaf(Gs[lane][rp], pv, y0);
            if (lane < 4) y1 = fmaf(Gs[32 + lane][rp], pv, y1);
        }
        float q = p0 * y0 + p1 * y1;
        #pragma unroll
        for (int o = 16; o; o >>= 1) q += __shfl_xor_sync(~0u, q, o);

        if (lane == 0) {
            float n = sqrtf(q);
            float denom = n + EPS_;
            float w12 = dot / denom;
            float w2v = n / denom;
            float w1v = sqrtf(d_capn[c * W_ + w]);
            float sim = w12 / fmaxf(w1v * w2v, EPS_);
            out[((size_t)i * C_ + c) * W_ + w] = sim;
        }
    }
}

// ============================================================
extern "C" void kernel_launch(void* const* d_in, const int* in_sizes, int n_in,
                              void* d_out, int out_size) {
    const float* imgs     = (const float*)d_in[0];
    const float* caps     = (const float*)d_in[1];
    const int*   cap_lens = (const int*)d_in[3];
    float* out = (float*)d_out;

    cudaFuncSetAttribute(gemm_mma_kernel, cudaFuncAttributeMaxDynamicSharedMemorySize, GEMM_SMEM);

    prep_kernel<<<1, C_>>>(cap_lens);
    convert_kernel<<<(ACH + BCH + 255) / 256, 256>>>(caps, imgs);
    capn_kernel<<<C_, 256>>>(caps);
    gram_kernel<<<I_, 256>>>(imgs);
    dim3 ggrid(N_ / BN, MROWS / BM);   // (18, 16)
    gemm_mma_kernel<<<ggrid, 256, GEMM_SMEM>>>();
    dim3 pgrid(I_, C_);
    post_kernel<<<pgrid, 128>>>(cap_lens, out);
}

// round 5
// speedup vs baseline: 2.1764x; 1.1801x over previous
#include <cuda_runtime.h>
#include <cuda_bf16.h>
#include <cstdint>
#include <math.h>

#define I_ 64
#define R_ 36
#define D_ 1024
#define C_ 64
#define W_ 32
#define N_ (I_*R_)       // 2304
#define MROWS (C_*W_)    // 2048
#define SMOOTH_ 9.0f
#define EPS_ 1e-8f
#define MASK_VAL_ (-1.0f)

// GEMM tiling
#define BM 128
#define BN 128
#define BK 32                    // bf16 k-elems per stage
#define NSTAGE (D_/BK)           // 32
#define ROWB 80                  // smem row stride bytes (5*16B: ldmatrix conflict-free)
#define TILEB (BM*ROWB)          // 10240 B per operand tile
#define GEMM_SMEM (2*4*TILEB)    // 81920 (2 stages x {Ah,Al,Bh,Bl})

// Gram k-split
#define GCH 8                    // 8 chunks of 128 d
#define GSZ (I_*R_*R_)           // 82944

// ---- static scratch ----
__device__ float d_S[MROWS * N_];          // raw logits, ~18.9MB
__device__ float d_G[GSZ];
__device__ float d_Gp[GCH][GSZ];           // partial grams, 2.65MB
__device__ float d_capn[C_ * W_];
__device__ int   d_rowmap[MROWS];
__device__ int   d_actoff[C_];
__device__ int   d_act_total;

// row-major gathered bf16 hi/lo operands
__device__ __nv_bfloat16 d_Ath[MROWS * D_];   // 4MB
__device__ __nv_bfloat16 d_Atl[MROWS * D_];
__device__ __nv_bfloat16 d_Bth[N_ * D_];      // 4.5MB
__device__ __nv_bfloat16 d_Btl[N_ * D_];

// ================= PTX helpers (baseline sm_80+/sm_90, no 'a' features) ====
__device__ __forceinline__ uint32_t smem_u32(const void* p) {
    uint32_t a;
    asm("{ .reg .u64 t; cvta.to.shared.u64 t, %1; cvt.u32.u64 %0, t; }" : "=r"(a) : "l"(p));
    return a;
}
__device__ __forceinline__ void cpasync16(uint32_t dst, const void* src) {
    asm volatile("cp.async.cg.shared.global [%0], [%1], 16;" :: "r"(dst), "l"(src) : "memory");
}
#define CP_COMMIT() asm volatile("cp.async.commit_group;" ::: "memory")
#define CP_WAIT(n)  asm volatile("cp.async.wait_group %0;" :: "n"(n) : "memory")

__device__ __forceinline__ void ldsm4(uint32_t r[4], uint32_t addr) {
    asm volatile("ldmatrix.sync.aligned.m8n8.x4.shared.b16 {%0,%1,%2,%3}, [%4];"
                 : "=r"(r[0]), "=r"(r[1]), "=r"(r[2]), "=r"(r[3]) : "r"(addr));
}
__device__ __forceinline__ void mma16816(float* d, const uint32_t* a, const uint32_t* b0, const uint32_t* b1) {
    asm volatile("mma.sync.aligned.m16n8k16.row.col.f32.bf16.bf16.f32 "
                 "{%0,%1,%2,%3},{%4,%5,%6,%7},{%8,%9},{%0,%1,%2,%3};"
                 : "+f"(d[0]), "+f"(d[1]), "+f"(d[2]), "+f"(d[3])
                 : "r"(a[0]), "r"(a[1]), "r"(a[2]), "r"(a[3]), "r"(*b0), "r"(*b1));
}

// ============================================================
// 0) compaction of active (c,w) rows
// ============================================================
__global__ void prep_kernel(const int* __restrict__ cap_lens) {
    __shared__ int offs[C_ + 1];
    int tid = threadIdx.x;
    if (tid == 0) {
        int run = 0;
        for (int c = 0; c < C_; c++) { offs[c] = run; run += cap_lens[c]; }
        offs[C_] = run;
        d_act_total = run;
    }
    __syncthreads();
    int c = tid;
    int off = offs[c], nw = cap_lens[c];
    d_actoff[c] = off;
    for (int w = 0; w < nw; w++) d_rowmap[off + w] = c * W_ + w;
    int total = offs[C_];
    for (int idx = total + tid; idx < MROWS; idx += C_) d_rowmap[idx] = 0;
}

// ============================================================
// 1) caption row norms
// ============================================================
__global__ void capn_kernel(const float* __restrict__ caps) {
    int c = blockIdx.x;
    int tid = threadIdx.x;
    int w = tid >> 3, l = tid & 7;
    const float* p = caps + ((size_t)(c * W_ + w)) * D_;
    float s = 0.f;
    for (int d = l; d < D_; d += 8) { float v = p[d]; s += v * v; }
    s += __shfl_down_sync(0xffffffffu, s, 4);
    s += __shfl_down_sync(0xffffffffu, s, 2);
    s += __shfl_down_sync(0xffffffffu, s, 1);
    if (l == 0) d_capn[c * W_ + w] = s;
}

// ============================================================
// 2) convert: fp32 -> bf16 hi/lo, row-major (A gathered via rowmap)
// ============================================================
#define ACH (MROWS * (D_/8))   // 262144
#define BCH (N_ * (D_/8))      // 294912
__global__ void convert_kernel(const float* __restrict__ caps, const float* __restrict__ imgs) {
    int t = blockIdx.x * 256 + threadIdx.x;
    const float* src;
    size_t dsto;
    __nv_bfloat16 *bh, *bl;
    if (t < ACH) {
        int row = t >> 7, c8 = t & 127;
        src = caps + (size_t)d_rowmap[row] * D_ + c8 * 8;
        dsto = (size_t)row * D_ + c8 * 8;
        bh = d_Ath; bl = d_Atl;
    } else if (t < ACH + BCH) {
        int u = t - ACH;
        int row = u >> 7, c8 = u & 127;
        src = imgs + (size_t)row * D_ + c8 * 8;
        dsto = (size_t)row * D_ + c8 * 8;
        bh = d_Bth; bl = d_Btl;
    } else return;

    float4 v0 = *reinterpret_cast<const float4*>(src);
    float4 v1 = *reinterpret_cast<const float4*>(src + 4);
    float v[8] = {v0.x, v0.y, v0.z, v0.w, v1.x, v1.y, v1.z, v1.w};
    union { __nv_bfloat16 h[8]; uint4 u; } Hi, Lo;
    #pragma unroll
    for (int k = 0; k < 8; k++) {
        __nv_bfloat16 hb = __float2bfloat16(v[k]);
        float r = v[k] - __bfloat162float(hb);
        Hi.h[k] = hb;
        Lo.h[k] = __float2bfloat16(r);
    }
    *reinterpret_cast<uint4*>(bh + dsto) = Hi.u;
    *reinterpret_cast<uint4*>(bl + dsto) = Lo.u;
}

// ============================================================
// 3) Gram matrices, k-split: grid = I_*GCH, 160 threads
//    each CTA: partial G over a 128-d chunk -> d_Gp[chunk]
// ============================================================
__global__ void __launch_bounds__(160) gram_kernel(const float* __restrict__ imgs) {
    __shared__ float sm[R_][132];      // row stride 132 floats (16B-aligned, padded)
    int blk = blockIdx.x;
    int i = blk >> 3, ch = blk & 7;
    int tid = threadIdx.x;
    const float* base = imgs + (size_t)i * R_ * D_ + ch * 128;

    for (int idx = tid; idx < R_ * 32; idx += 160) {
        int r = idx >> 5, d4 = idx & 31;
        float4 v = *reinterpret_cast<const float4*>(base + r * D_ + d4 * 4);
        *reinterpret_cast<float4*>(&sm[r][d4 * 4]) = v;
    }
    __syncthreads();

    if (tid < 144) {
        int tr = tid / 12, tc = tid % 12;
        float acc[3][3] = {};
        #pragma unroll 2
        for (int d = 0; d < 128; d += 4) {
            float4 A0 = *reinterpret_cast<const float4*>(&sm[tr*3+0][d]);
            float4 A1 = *reinterpret_cast<const float4*>(&sm[tr*3+1][d]);
            float4 A2 = *reinterpret_cast<const float4*>(&sm[tr*3+2][d]);
            float4 B0 = *reinterpret_cast<const float4*>(&sm[tc*3+0][d]);
            float4 B1 = *reinterpret_cast<const float4*>(&sm[tc*3+1][d]);
            float4 B2 = *reinterpret_cast<const float4*>(&sm[tc*3+2][d]);
            acc[0][0] = fmaf(A0.x,B0.x,fmaf(A0.y,B0.y,fmaf(A0.z,B0.z,fmaf(A0.w,B0.w,acc[0][0]))));
            acc[0][1] = fmaf(A0.x,B1.x,fmaf(A0.y,B1.y,fmaf(A0.z,B1.z,fmaf(A0.w,B1.w,acc[0][1]))));
            acc[0][2] = fmaf(A0.x,B2.x,fmaf(A0.y,B2.y,fmaf(A0.z,B2.z,fmaf(A0.w,B2.w,acc[0][2]))));
            acc[1][0] = fmaf(A1.x,B0.x,fmaf(A1.y,B0.y,fmaf(A1.z,B0.z,fmaf(A1.w,B0.w,acc[1][0]))));
            acc[1][1] = fmaf(A1.x,B1.x,fmaf(A1.y,B1.y,fmaf(A1.z,B1.z,fmaf(A1.w,B1.w,acc[1][1]))));
            acc[1][2] = fmaf(A1.x,B2.x,fmaf(A1.y,B2.y,fmaf(A1.z,B2.z,fmaf(A1.w,B2.w,acc[1][2]))));
            acc[2][0] = fmaf(A2.x,B0.x,fmaf(A2.y,B0.y,fmaf(A2.z,B0.z,fmaf(A2.w,B0.w,acc[2][0]))));
            acc[2][1] = fmaf(A2.x,B1.x,fmaf(A2.y,B1.y,fmaf(A2.z,B1.z,fmaf(A2.w,B1.w,acc[2][1]))));
            acc[2][2] = fmaf(A2.x,B2.x,fmaf(A2.y,B2.y,fmaf(A2.z,B2.z,fmaf(A2.w,B2.w,acc[2][2]))));
        }
        float* dst = d_Gp[ch] + i * (R_*R_);
        #pragma unroll
        for (int a = 0; a < 3; a++)
            #pragma unroll
            for (int b = 0; b < 3; b++)
                dst[(tr*3+a) * R_ + (tc*3+b)] = acc[a][b];
    }
}

// reduce 8 partials -> d_G (deterministic)
__global__ void gram_reduce_kernel() {
    int t = blockIdx.x * 256 + threadIdx.x;
    if (t >= GSZ) return;
    float s = 0.f;
    #pragma unroll
    for (int p = 0; p < GCH; p++) s += d_Gp[p][t];
    d_G[t] = s;
}

// ============================================================
// 4) HMMA bf16x3 GEMM: S = A_gathered . B^T
// ============================================================
__global__ void __launch_bounds__(256, 1) gemm_mma_kernel() {
    extern __shared__ __align__(128) char smc[];
    uint32_t sb = smem_u32(smc);
    int tid = threadIdx.x, wid = tid >> 5, lane = tid & 31;

    int act = d_act_total;
    int mblk = blockIdx.y;
    if (mblk * BM >= act) return;
    int nblk = blockIdx.x;

    int wr = wid & 1, wc = wid >> 1;

    const __nv_bfloat16* srcs[4] = {
        d_Ath + (size_t)mblk * BM * D_,
        d_Atl + (size_t)mblk * BM * D_,
        d_Bth + (size_t)nblk * BN * D_,
        d_Btl + (size_t)nblk * BN * D_
    };

    int q = lane >> 3, lr = lane & 7;
    int rowoff = ((q & 1) << 3) + lr;
    int csel = q >> 1;
    uint32_t aoff = (uint32_t)((wr * 64 + rowoff) * ROWB + csel * 16);
    uint32_t boff = (uint32_t)((wc * 32 + rowoff) * ROWB + csel * 16);

    float acc[4][4][4] = {};

    #define LOAD_STAGE(s, k0) do {                                              \
        _Pragma("unroll")                                                        \
        for (int it = 0; it < 8; it++) {                                         \
            int ci = tid + it * 256;                                             \
            int tt = ci >> 9, r2 = ci & 511;                                     \
            int row = r2 >> 2, cc = r2 & 3;                                      \
            const char* g = (const char*)(srcs[tt] + (size_t)row * D_ + (k0)) + cc * 16; \
            uint32_t dd = sb + (uint32_t)(((s) * 4 + tt) * TILEB + row * ROWB + cc * 16); \
            cpasync16(dd, g);                                                    \
        }                                                                        \
        CP_COMMIT();                                                             \
    } while (0)

    LOAD_STAGE(0, 0);

    for (int ks = 0; ks < NSTAGE; ks++) {
        int s = ks & 1;
        if (ks + 1 < NSTAGE) { LOAD_STAGE(s ^ 1, (ks + 1) * BK); CP_WAIT(1); }
        else                 { CP_WAIT(0); }
        __syncthreads();

        uint32_t bAh = sb + (uint32_t)((s * 4 + 0) * TILEB);
        uint32_t bAl = sb + (uint32_t)((s * 4 + 1) * TILEB);
        uint32_t bBh = sb + (uint32_t)((s * 4 + 2) * TILEB);
        uint32_t bBl = sb + (uint32_t)((s * 4 + 3) * TILEB);

        #pragma unroll
        for (int k16 = 0; k16 < 2; k16++) {
            uint32_t kb = (uint32_t)(k16 * 32);
            uint32_t ah[4][4], al[4][4];
            uint32_t bhf[4][2], blf[4][2];
            #pragma unroll
            for (int mt = 0; mt < 4; mt++) {
                ldsm4(ah[mt], bAh + (uint32_t)(mt * 16 * ROWB) + kb + aoff);
                ldsm4(al[mt], bAl + (uint32_t)(mt * 16 * ROWB) + kb + aoff);
            }
            #pragma unroll
            for (int np = 0; np < 2; np++) {
                uint32_t t4[4];
                ldsm4(t4, bBh + (uint32_t)(np * 16 * ROWB) + kb + boff);
                bhf[np*2+0][0] = t4[0]; bhf[np*2+0][1] = t4[2];
                bhf[np*2+1][0] = t4[1]; bhf[np*2+1][1] = t4[3];
                ldsm4(t4, bBl + (uint32_t)(np * 16 * ROWB) + kb + boff);
                blf[np*2+0][0] = t4[0]; blf[np*2+0][1] = t4[2];
                blf[np*2+1][0] = t4[1]; blf[np*2+1][1] = t4[3];
            }
            #pragma unroll
            for (int mt = 0; mt < 4; mt++)
                #pragma unroll
                for (int nt = 0; nt < 4; nt++) {
                    mma16816(acc[mt][nt], ah[mt], &bhf[nt][0], &bhf[nt][1]);
                    mma16816(acc[mt][nt], ah[mt], &blf[nt][0], &blf[nt][1]);
                    mma16816(acc[mt][nt], al[mt], &bhf[nt][0], &bhf[nt][1]);
                }
        }
        __syncthreads();
    }

    int g = lane >> 2, tq = lane & 3;
    #pragma unroll
    for (int mt = 0; mt < 4; mt++) {
        int m0 = mblk * BM + wr * 64 + mt * 16 + g;
        #pragma unroll
        for (int nt = 0; nt < 4; nt++) {
            int n = nblk * BN + wc * 32 + nt * 8 + tq * 2;
            if (m0 < act)
                *reinterpret_cast<float2*>(d_S + (size_t)m0 * N_ + n) =
                    make_float2(acc[mt][nt][0], acc[mt][nt][1]);
            if (m0 + 8 < act)
                *reinterpret_cast<float2*>(d_S + (size_t)(m0 + 8) * N_ + n) =
                    make_float2(acc[mt][nt][2], acc[mt][nt][3]);
        }
    }
}

// ============================================================
// 5) epilogue per (c,i)
// ============================================================
__global__ void __launch_bounds__(128) post_kernel(const int* __restrict__ cap_lens,
                                                   float* __restrict__ out) {
    int i = blockIdx.x, c = blockIdx.y;
    int tid = threadIdx.x;
    int lane = tid & 31, wid = tid >> 5;
    int nw = cap_lens[c], m0 = d_actoff[c];

    __shared__ float Ss[W_][37];
    __shared__ float Gs[R_][37];
    __shared__ float cn[R_];

    if (tid < W_ && tid >= nw)
        out[((size_t)i * C_ + c) * W_ + tid] = MASK_VAL_;

    for (int idx = tid; idx < R_ * R_; idx += 128)
        Gs[idx / R_][idx % R_] = d_G[i * R_ * R_ + idx];
    for (int idx = tid; idx < nw * R_; idx += 128) {
        int w = idx / R_, r = idx - w * R_;
        Ss[w][r] = d_S[(size_t)(m0 + w) * N_ + i * R_ + r];
    }
    __syncthreads();

    if (tid < R_) {
        float s = 0.f;
        for (int w = 0; w < nw; w++) {
            float v = Ss[w][tid];
            v = (v >= 0.f) ? v : 0.1f * v;
            s += v * v;
        }
        cn[tid] = sqrtf(s) + EPS_;
    }
    __syncthreads();

    for (int w = wid; w < nw; w += 4) {
        float s0 = Ss[w][lane];
        float s1 = (lane < 4) ? Ss[w][32 + lane] : 0.f;
        float l0 = (s0 >= 0.f) ? s0 : 0.1f * s0;
        float l1 = (s1 >= 0.f) ? s1 : 0.1f * s1;
        float a0 = l0 / cn[lane] * SMOOTH_;
        float a1 = (lane < 4) ? (l1 / cn[32 + lane] * SMOOTH_) : -1e30f;

        float mx = fmaxf(a0, a1);
        #pragma unroll
        for (int o = 16; o; o >>= 1) mx = fmaxf(mx, __shfl_xor_sync(~0u, mx, o));
        float e0 = expf(a0 - mx);
        float e1 = (lane < 4) ? expf(a1 - mx) : 0.f;
        float sum = e0 + e1;
        #pragma unroll
        for (int o = 16; o; o >>= 1) sum += __shfl_xor_sync(~0u, sum, o);
        float p0 = e0 / sum, p1 = e1 / sum;

        float dot = p0 * s0 + p1 * s1;
        #pragma unroll
        for (int o = 16; o; o >>= 1) dot += __shfl_xor_sync(~0u, dot, o);

        float y0 = 0.f, y1 = 0.f;
        #pragma unroll 4
        for (int rp = 0; rp < R_; rp++) {
            float pv = (rp < 32) ? __shfl_sync(~0u, p0, rp)
                                 : __shfl_sync(~0u, p1, rp - 32);
            y0 = fmaf(Gs[lane][rp], pv, y0);
            if (lane < 4) y1 = fmaf(Gs[32 + lane][rp], pv, y1);
        }
        float q = p0 * y0 + p1 * y1;
        #pragma unroll
        for (int o = 16; o; o >>= 1) q += __shfl_xor_sync(~0u, q, o);

        if (lane == 0) {
            float n = sqrtf(q);
            float denom = n + EPS_;
            float w12 = dot / denom;
            float w2v = n / denom;
            float w1v = sqrtf(d_capn[c * W_ + w]);
            float sim = w12 / fmaxf(w1v * w2v, EPS_);
            out[((size_t)i * C_ + c) * W_ + w] = sim;
        }
    }
}

// ============================================================
extern "C" void kernel_launch(void* const* d_in, const int* in_sizes, int n_in,
                              void* d_out, int out_size) {
    const float* imgs     = (const float*)d_in[0];
    const float* caps     = (const float*)d_in[1];
    const int*   cap_lens = (const int*)d_in[3];
    float* out = (float*)d_out;

    cudaFuncSetAttribute(gemm_mma_kernel, cudaFuncAttributeMaxDynamicSharedMemorySize, GEMM_SMEM);

    prep_kernel<<<1, C_>>>(cap_lens);
    convert_kernel<<<(ACH + BCH + 255) / 256, 256>>>(caps, imgs);
    capn_kernel<<<C_, 256>>>(caps);
    gram_kernel<<<I_ * GCH, 160>>>(imgs);
    gram_reduce_kernel<<<(GSZ + 255) / 256, 256>>>();
    dim3 ggrid(N_ / BN, MROWS / BM);   // (18, 16)
    gemm_mma_kernel<<<ggrid, 256, GEMM_SMEM>>>();
    dim3 pgrid(I_, C_);
    post_kernel<<<pgrid, 128>>>(cap_lens, out);
}

// round 6
// speedup vs baseline: 2.2103x; 1.0156x over previous
#include <cuda_runtime.h>
#include <cuda_bf16.h>
#include <cstdint>
#include <math.h>

#define I_ 64
#define R_ 36
#define D_ 1024
#define C_ 64
#define W_ 32
#define N_ (I_*R_)       // 2304
#define MROWS (C_*W_)    // 2048
#define SMOOTH_ 9.0f
#define EPS_ 1e-8f
#define MASK_VAL_ (-1.0f)

// GEMM tiling (BM=64 for wave balance)
#define BM 64
#define BN 128
#define BK 32                    // bf16 k-elems per stage
#define NSTAGE (D_/BK)           // 32
#define ROWB 80                  // smem row stride bytes (5*16B: ldmatrix conflict-free)
#define TA (BM*ROWB)             // 5120 B  (A tile)
#define TB (BN*ROWB)             // 10240 B (B tile)
#define STGB (2*TA + 2*TB)       // 30720 B per stage
#define GEMM_SMEM (2*STGB)       // 61440
#define MB2 (MROWS/BM)           // 32 m-blocks
#define NB2 (N_/BN)              // 18 n-blocks

// Gram k-split
#define GCH 8
#define GSZ (I_*R_*R_)           // 82944

// mega-kernel partition
#define ACH (MROWS * (D_/8))     // 262144
#define BCH (N_ * (D_/8))        // 294912
#define CONVB ((ACH + BCH) / 256) // 2176
#define GRAMB (I_ * GCH)          // 512
#define CAPNB C_                  // 64
#define MEGAB (CONVB + GRAMB + CAPNB)

// ---- static scratch ----
__device__ float d_S[MROWS * N_];
__device__ float d_G[GSZ];
__device__ float d_Gp[GCH][GSZ];
__device__ float d_capn[C_ * W_];
__device__ int   d_rowmap[MROWS];
__device__ int   d_actoff[C_];
__device__ int   d_act_total;

__device__ __nv_bfloat16 d_Ath[MROWS * D_];
__device__ __nv_bfloat16 d_Atl[MROWS * D_];
__device__ __nv_bfloat16 d_Bth[N_ * D_];
__device__ __nv_bfloat16 d_Btl[N_ * D_];

// ================= PTX helpers =================
__device__ __forceinline__ uint32_t smem_u32(const void* p) {
    uint32_t a;
    asm("{ .reg .u64 t; cvta.to.shared.u64 t, %1; cvt.u32.u64 %0, t; }" : "=r"(a) : "l"(p));
    return a;
}
__device__ __forceinline__ void cpasync16(uint32_t dst, const void* src) {
    asm volatile("cp.async.cg.shared.global [%0], [%1], 16;" :: "r"(dst), "l"(src) : "memory");
}
#define CP_COMMIT() asm volatile("cp.async.commit_group;" ::: "memory")
#define CP_WAIT(n)  asm volatile("cp.async.wait_group %0;" :: "n"(n) : "memory")

__device__ __forceinline__ void ldsm4(uint32_t r[4], uint32_t addr) {
    asm volatile("ldmatrix.sync.aligned.m8n8.x4.shared.b16 {%0,%1,%2,%3}, [%4];"
                 : "=r"(r[0]), "=r"(r[1]), "=r"(r[2]), "=r"(r[3]) : "r"(addr));
}
__device__ __forceinline__ void mma16816(float* d, const uint32_t* a, const uint32_t* b0, const uint32_t* b1) {
    asm volatile("mma.sync.aligned.m16n8k16.row.col.f32.bf16.bf16.f32 "
                 "{%0,%1,%2,%3},{%4,%5,%6,%7},{%8,%9},{%0,%1,%2,%3};"
                 : "+f"(d[0]), "+f"(d[1]), "+f"(d[2]), "+f"(d[3])
                 : "r"(a[0]), "r"(a[1]), "r"(a[2]), "r"(a[3]), "r"(*b0), "r"(*b1));
}

// ============================================================
// 0) compaction of active (c,w) rows
// ============================================================
__global__ void prep_kernel(const int* __restrict__ cap_lens) {
    __shared__ int offs[C_ + 1];
    int tid = threadIdx.x;
    if (tid == 0) {
        int run = 0;
        for (int c = 0; c < C_; c++) { offs[c] = run; run += cap_lens[c]; }
        offs[C_] = run;
        d_act_total = run;
    }
    __syncthreads();
    int c = tid;
    int off = offs[c], nw = cap_lens[c];
    d_actoff[c] = off;
    for (int w = 0; w < nw; w++) d_rowmap[off + w] = c * W_ + w;
    int total = offs[C_];
    for (int idx = total + tid; idx < MROWS; idx += C_) d_rowmap[idx] = 0;
}

// ============================================================
// mega kernel: convert (blocks 0..CONVB) + gram (next GRAMB) + capn (next 64)
// ============================================================
__device__ __forceinline__ void do_convert(int t, const float* __restrict__ caps,
                                           const float* __restrict__ imgs) {
    const float* src;
    size_t dsto;
    __nv_bfloat16 *bh, *bl;
    if (t < ACH) {
        int row = t >> 7, c8 = t & 127;
        src = caps + (size_t)d_rowmap[row] * D_ + c8 * 8;
        dsto = (size_t)row * D_ + c8 * 8;
        bh = d_Ath; bl = d_Atl;
    } else {
        int u = t - ACH;
        int row = u >> 7, c8 = u & 127;
        src = imgs + (size_t)row * D_ + c8 * 8;
        dsto = (size_t)row * D_ + c8 * 8;
        bh = d_Bth; bl = d_Btl;
    }
    float4 v0 = *reinterpret_cast<const float4*>(src);
    float4 v1 = *reinterpret_cast<const float4*>(src + 4);
    float v[8] = {v0.x, v0.y, v0.z, v0.w, v1.x, v1.y, v1.z, v1.w};
    union { __nv_bfloat16 h[8]; uint4 u; } Hi, Lo;
    #pragma unroll
    for (int k = 0; k < 8; k++) {
        __nv_bfloat16 hb = __float2bfloat16(v[k]);
        float r = v[k] - __bfloat162float(hb);
        Hi.h[k] = hb;
        Lo.h[k] = __float2bfloat16(r);
    }
    *reinterpret_cast<uint4*>(bh + dsto) = Hi.u;
    *reinterpret_cast<uint4*>(bl + dsto) = Lo.u;
}

__global__ void __launch_bounds__(256) mega_kernel(const float* __restrict__ caps,
                                                   const float* __restrict__ imgs) {
    __shared__ float sm[R_][132];
    int b = blockIdx.x, tid = threadIdx.x;

    if (b < CONVB) {
        do_convert(b * 256 + tid, caps, imgs);
        return;
    }
    if (b < CONVB + GRAMB) {
        int gb = b - CONVB;
        int i = gb >> 3, ch = gb & 7;
        const float* base = imgs + (size_t)i * R_ * D_ + ch * 128;
        for (int idx = tid; idx < R_ * 32; idx += 256) {
            int r = idx >> 5, d4 = idx & 31;
            float4 v = *reinterpret_cast<const float4*>(base + r * D_ + d4 * 4);
            *reinterpret_cast<float4*>(&sm[r][d4 * 4]) = v;
        }
        __syncthreads();
        if (tid < 144) {
            int tr = tid / 12, tc = tid % 12;
            float acc[3][3] = {};
            #pragma unroll 2
            for (int d = 0; d < 128; d += 4) {
                float4 A0 = *reinterpret_cast<const float4*>(&sm[tr*3+0][d]);
                float4 A1 = *reinterpret_cast<const float4*>(&sm[tr*3+1][d]);
                float4 A2 = *reinterpret_cast<const float4*>(&sm[tr*3+2][d]);
                float4 B0 = *reinterpret_cast<const float4*>(&sm[tc*3+0][d]);
                float4 B1 = *reinterpret_cast<const float4*>(&sm[tc*3+1][d]);
                float4 B2 = *reinterpret_cast<const float4*>(&sm[tc*3+2][d]);
                acc[0][0] = fmaf(A0.x,B0.x,fmaf(A0.y,B0.y,fmaf(A0.z,B0.z,fmaf(A0.w,B0.w,acc[0][0]))));
                acc[0][1] = fmaf(A0.x,B1.x,fmaf(A0.y,B1.y,fmaf(A0.z,B1.z,fmaf(A0.w,B1.w,acc[0][1]))));
                acc[0][2] = fmaf(A0.x,B2.x,fmaf(A0.y,B2.y,fmaf(A0.z,B2.z,fmaf(A0.w,B2.w,acc[0][2]))));
                acc[1][0] = fmaf(A1.x,B0.x,fmaf(A1.y,B0.y,fmaf(A1.z,B0.z,fmaf(A1.w,B0.w,acc[1][0]))));
                acc[1][1] = fmaf(A1.x,B1.x,fmaf(A1.y,B1.y,fmaf(A1.z,B1.z,fmaf(A1.w,B1.w,acc[1][1]))));
                acc[1][2] = fmaf(A1.x,B2.x,fmaf(A1.y,B2.y,fmaf(A1.z,B2.z,fmaf(A1.w,B2.w,acc[1][2]))));
                acc[2][0] = fmaf(A2.x,B0.x,fmaf(A2.y,B0.y,fmaf(A2.z,B0.z,fmaf(A2.w,B0.w,acc[2][0]))));
                acc[2][1] = fmaf(A2.x,B1.x,fmaf(A2.y,B1.y,fmaf(A2.z,B1.z,fmaf(A2.w,B1.w,acc[2][1]))));
                acc[2][2] = fmaf(A2.x,B2.x,fmaf(A2.y,B2.y,fmaf(A2.z,B2.z,fmaf(A2.w,B2.w,acc[2][2]))));
            }
            float* dst = d_Gp[ch] + i * (R_*R_);
            #pragma unroll
            for (int a = 0; a < 3; a++)
                #pragma unroll
                for (int bb = 0; bb < 3; bb++)
                    dst[(tr*3+a) * R_ + (tc*3+bb)] = acc[a][bb];
        }
        return;
    }
    // capn
    {
        int c = b - (CONVB + GRAMB);
        int w = tid >> 3, l = tid & 7;
        const float* p = caps + ((size_t)(c * W_ + w)) * D_;
        float s = 0.f;
        for (int d = l; d < D_; d += 8) { float v = p[d]; s += v * v; }
        s += __shfl_down_sync(0xffffffffu, s, 4);
        s += __shfl_down_sync(0xffffffffu, s, 2);
        s += __shfl_down_sync(0xffffffffu, s, 1);
        if (l == 0) d_capn[c * W_ + w] = s;
    }
}

// ============================================================
// HMMA bf16x3 GEMM (BM=64, 2 CTAs/SM) + fused gram reduce row
// ============================================================
__global__ void __launch_bounds__(256, 2) gemm_mma_kernel() {
    extern __shared__ __align__(128) char smc[];
    int tid = threadIdx.x;

    // appended gram-reduce row
    if (blockIdx.y == MB2) {
        for (int t = blockIdx.x * 256 + tid; t < GSZ; t += NB2 * 256) {
            float s = 0.f;
            #pragma unroll
            for (int p = 0; p < GCH; p++) s += d_Gp[p][t];
            d_G[t] = s;
        }
        return;
    }

    uint32_t sb = smem_u32(smc);
    int wid = tid >> 5, lane = tid & 31;

    int act = d_act_total;
    int mblk = blockIdx.y;
    if (mblk * BM >= act) return;
    int nblk = blockIdx.x;

    int wr = wid & 1, wc = wid >> 1;   // 2x4 warps: 32-row x 32-col tiles

    const __nv_bfloat16* srcA[2] = {
        d_Ath + (size_t)mblk * BM * D_,
        d_Atl + (size_t)mblk * BM * D_
    };
    const __nv_bfloat16* srcB[2] = {
        d_Bth + (size_t)nblk * BN * D_,
        d_Btl + (size_t)nblk * BN * D_
    };

    int q = lane >> 3, lr = lane & 7;
    int rowoff = ((q & 1) << 3) + lr;
    int csel = q >> 1;
    uint32_t aoff = (uint32_t)((wr * 32 + rowoff) * ROWB + csel * 16);
    uint32_t boff = (uint32_t)((wc * 32 + rowoff) * ROWB + csel * 16);

    float acc[2][4][4] = {};

    // per stage: A tiles 2x256 chunks, B tiles 2x512 chunks => 1536; 6/thread
    #define LOAD_STAGE(s, k0) do {                                              \
        _Pragma("unroll")                                                        \
        for (int it = 0; it < 6; it++) {                                         \
            int ci = tid + it * 256;                                             \
            const char* g; uint32_t dd;                                          \
            if (ci < 512) {                                                      \
                int tt = ci >> 8, r2 = ci & 255;                                  \
                int row = r2 >> 2, cc = r2 & 3;                                   \
                g = (const char*)(srcA[tt] + (size_t)row * D_ + (k0)) + cc * 16;  \
                dd = sb + (uint32_t)((s) * STGB + tt * TA + row * ROWB + cc * 16);\
            } else {                                                              \
                int u = ci - 512;                                                 \
                int tt = u >> 9, r2 = u & 511;                                    \
                int row = r2 >> 2, cc = r2 & 3;                                   \
                g = (const char*)(srcB[tt] + (size_t)row * D_ + (k0)) + cc * 16;  \
                dd = sb + (uint32_t)((s) * STGB + 2 * TA + tt * TB + row * ROWB + cc * 16); \
            }                                                                     \
            cpasync16(dd, g);                                                     \
        }                                                                         \
        CP_COMMIT();                                                              \
    } while (0)

    LOAD_STAGE(0, 0);

    for (int ks = 0; ks < NSTAGE; ks++) {
        int s = ks & 1;
        if (ks + 1 < NSTAGE) { LOAD_STAGE(s ^ 1, (ks + 1) * BK); CP_WAIT(1); }
        else                 { CP_WAIT(0); }
        __syncthreads();

        uint32_t bAh = sb + (uint32_t)(s * STGB);
        uint32_t bAl = bAh + TA;
        uint32_t bBh = bAh + 2 * TA;
        uint32_t bBl = bBh + TB;

        #pragma unroll
        for (int k16 = 0; k16 < 2; k16++) {
            uint32_t kb = (uint32_t)(k16 * 32);
            uint32_t ah[2][4], al[2][4];
            uint32_t bhf[4][2], blf[4][2];
            #pragma unroll
            for (int mt = 0; mt < 2; mt++) {
                ldsm4(ah[mt], bAh + (uint32_t)(mt * 16 * ROWB) + kb + aoff);
                ldsm4(al[mt], bAl + (uint32_t)(mt * 16 * ROWB) + kb + aoff);
            }
            #pragma unroll
            for (int np = 0; np < 2; np++) {
                uint32_t t4[4];
                ldsm4(t4, bBh + (uint32_t)(np * 16 * ROWB) + kb + boff);
                bhf[np*2+0][0] = t4[0]; bhf[np*2+0][1] = t4[2];
                bhf[np*2+1][0] = t4[1]; bhf[np*2+1][1] = t4[3];
                ldsm4(t4, bBl + (uint32_t)(np * 16 * ROWB) + kb + boff);
                blf[np*2+0][0] = t4[0]; blf[np*2+0][1] = t4[2];
                blf[np*2+1][0] = t4[1]; blf[np*2+1][1] = t4[3];
            }
            #pragma unroll
            for (int mt = 0; mt < 2; mt++)
                #pragma unroll
                for (int nt = 0; nt < 4; nt++) {
                    mma16816(acc[mt][nt], ah[mt], &bhf[nt][0], &bhf[nt][1]);
                    mma16816(acc[mt][nt], ah[mt], &blf[nt][0], &blf[nt][1]);
                    mma16816(acc[mt][nt], al[mt], &bhf[nt][0], &bhf[nt][1]);
                }
        }
        __syncthreads();
    }

    int g = lane >> 2, tq = lane & 3;
    #pragma unroll
    for (int mt = 0; mt < 2; mt++) {
        int m0 = mblk * BM + wr * 32 + mt * 16 + g;
        #pragma unroll
        for (int nt = 0; nt < 4; nt++) {
            int n = nblk * BN + wc * 32 + nt * 8 + tq * 2;
            if (m0 < act)
                *reinterpret_cast<float2*>(d_S + (size_t)m0 * N_ + n) =
                    make_float2(acc[mt][nt][0], acc[mt][nt][1]);
            if (m0 + 8 < act)
                *reinterpret_cast<float2*>(d_S + (size_t)(m0 + 8) * N_ + n) =
                    make_float2(acc[mt][nt][2], acc[mt][nt][3]);
        }
    }
}

// ============================================================
// epilogue per (c,i)
// ============================================================
__global__ void __launch_bounds__(128) post_kernel(const int* __restrict__ cap_lens,
                                                   float* __restrict__ out) {
    int i = blockIdx.x, c = blockIdx.y;
    int tid = threadIdx.x;
    int lane = tid & 31, wid = tid >> 5;
    int nw = cap_lens[c], m0 = d_actoff[c];

    __shared__ float Ss[W_][37];
    __shared__ float Gs[R_][37];
    __shared__ float cn[R_];

    if (tid < W_ && tid >= nw)
        out[((size_t)i * C_ + c) * W_ + tid] = MASK_VAL_;

    for (int idx = tid; idx < R_ * R_; idx += 128)
        Gs[idx / R_][idx % R_] = d_G[i * R_ * R_ + idx];
    for (int idx = tid; idx < nw * R_; idx += 128) {
        int w = idx / R_, r = idx - w * R_;
        Ss[w][r] = d_S[(size_t)(m0 + w) * N_ + i * R_ + r];
    }
    __syncthreads();

    if (tid < R_) {
        float s = 0.f;
        for (int w = 0; w < nw; w++) {
            float v = Ss[w][tid];
            v = (v >= 0.f) ? v : 0.1f * v;
            s += v * v;
        }
        cn[tid] = sqrtf(s) + EPS_;
    }
    __syncthreads();

    for (int w = wid; w < nw; w += 4) {
        float s0 = Ss[w][lane];
        float s1 = (lane < 4) ? Ss[w][32 + lane] : 0.f;
        float l0 = (s0 >= 0.f) ? s0 : 0.1f * s0;
        float l1 = (s1 >= 0.f) ? s1 : 0.1f * s1;
        float a0 = l0 / cn[lane] * SMOOTH_;
        float a1 = (lane < 4) ? (l1 / cn[32 + lane] * SMOOTH_) : -1e30f;

        float mx = fmaxf(a0, a1);
        #pragma unroll
        for (int o = 16; o; o >>= 1) mx = fmaxf(mx, __shfl_xor_sync(~0u, mx, o));
        float e0 = expf(a0 - mx);
        float e1 = (lane < 4) ? expf(a1 - mx) : 0.f;
        float sum = e0 + e1;
        #pragma unroll
        for (int o = 16; o; o >>= 1) sum += __shfl_xor_sync(~0u, sum, o);
        float p0 = e0 / sum, p1 = e1 / sum;

        float dot = p0 * s0 + p1 * s1;
        #pragma unroll
        for (int o = 16; o; o >>= 1) dot += __shfl_xor_sync(~0u, dot, o);

        float y0 = 0.f, y1 = 0.f;
        #pragma unroll 4
        for (int rp = 0; rp < R_; rp++) {
            float pv = (rp < 32) ? __shfl_sync(~0u, p0, rp)
                                 : __shfl_sync(~0u, p1, rp - 32);
            y0 = fmaf(Gs[lane][rp], pv, y0);
            if (lane < 4) y1 = fmaf(Gs[32 + lane][rp], pv, y1);
        }
        float q = p0 * y0 + p1 * y1;
        #pragma unroll
        for (int o = 16; o; o >>= 1) q += __shfl_xor_sync(~0u, q, o);

        if (lane == 0) {
            float n = sqrtf(q);
            float denom = n + EPS_;
            float w12 = dot / denom;
            float w2v = n / denom;
            float w1v = sqrtf(d_capn[c * W_ + w]);
            float sim = w12 / fmaxf(w1v * w2v, EPS_);
            out[((size_t)i * C_ + c) * W_ + w] = sim;
        }
    }
}

// ============================================================
extern "C" void kernel_launch(void* const* d_in, const int* in_sizes, int n_in,
                              void* d_out, int out_size) {
    const float* imgs     = (const float*)d_in[0];
    const float* caps     = (const float*)d_in[1];
    const int*   cap_lens = (const int*)d_in[3];
    float* out = (float*)d_out;

    cudaFuncSetAttribute(gemm_mma_kernel, cudaFuncAttributeMaxDynamicSharedMemorySize, GEMM_SMEM);

    prep_kernel<<<1, C_>>>(cap_lens);
    mega_kernel<<<MEGAB, 256>>>(caps, imgs);
    dim3 ggrid(NB2, MB2 + 1);   // (18, 33): last y-row = gram reduce
    gemm_mma_kernel<<<ggrid, 256, GEMM_SMEM>>>();
    dim3 pgrid(I_, C_);
    post_kernel<<<pgrid, 128>>>(cap_lens, out);
}

// round 7
// speedup vs baseline: 2.4651x; 1.1153x over previous
#include <cuda_runtime.h>
#include <cuda_bf16.h>
#include <cstdint>
#include <math.h>

#define I_ 64
#define R_ 36
#define D_ 1024
#define C_ 64
#define W_ 32
#define N_ (I_*R_)       // 2304
#define MROWS (C_*W_)    // 2048
#define SMOOTH_ 9.0f
#define EPS_ 1e-8f
#define MASK_VAL_ (-1.0f)

// GEMM tiling (BM=64 for wave balance)
#define BM 64
#define BN 128
#define BK 32
#define NSTAGE (D_/BK)           // 32
#define ROWB 80
#define TA (BM*ROWB)             // 5120
#define TB (BN*ROWB)             // 10240
#define STGB (2*TA + 2*TB)       // 30720
#define GEMM_SMEM (2*STGB)       // 61440
#define MB2 (MROWS/BM)           // 32
#define NB2 (N_/BN)              // 18

// Gram k-split
#define GCH 8
#define GSZ (I_*R_*R_)           // 82944

// mega-kernel partition
#define ACH (MROWS * (D_/8))     // 262144
#define BCH (N_ * (D_/8))        // 294912
#define CONVB ((ACH + BCH) / 256) // 2176
#define GRAMB (I_ * GCH)          // 512
#define CAPNB C_                  // 64
#define MEGAB (CONVB + GRAMB + CAPNB)

// ---- static scratch ----
__device__ float d_S[MROWS * N_];
__device__ float d_G[GSZ];
__device__ float d_Gp[GCH][GSZ];
__device__ float d_capn[C_ * W_];
__device__ int   d_rowmap[MROWS];
__device__ int   d_actoff[C_];
__device__ int   d_act_total;

__device__ __nv_bfloat16 d_Ath[MROWS * D_];
__device__ __nv_bfloat16 d_Atl[MROWS * D_];
__device__ __nv_bfloat16 d_Bth[N_ * D_];
__device__ __nv_bfloat16 d_Btl[N_ * D_];

// ================= PTX helpers =================
__device__ __forceinline__ uint32_t smem_u32(const void* p) {
    uint32_t a;
    asm("{ .reg .u64 t; cvta.to.shared.u64 t, %1; cvt.u32.u64 %0, t; }" : "=r"(a) : "l"(p));
    return a;
}
__device__ __forceinline__ void cpasync16(uint32_t dst, const void* src) {
    asm volatile("cp.async.cg.shared.global [%0], [%1], 16;" :: "r"(dst), "l"(src) : "memory");
}
#define CP_COMMIT() asm volatile("cp.async.commit_group;" ::: "memory")
#define CP_WAIT(n)  asm volatile("cp.async.wait_group %0;" :: "n"(n) : "memory")

__device__ __forceinline__ void ldsm4(uint32_t r[4], uint32_t addr) {
    asm volatile("ldmatrix.sync.aligned.m8n8.x4.shared.b16 {%0,%1,%2,%3}, [%4];"
                 : "=r"(r[0]), "=r"(r[1]), "=r"(r[2]), "=r"(r[3]) : "r"(addr));
}
__device__ __forceinline__ void mma16816(float* d, const uint32_t* a, const uint32_t* b0, const uint32_t* b1) {
    asm volatile("mma.sync.aligned.m16n8k16.row.col.f32.bf16.bf16.f32 "
                 "{%0,%1,%2,%3},{%4,%5,%6,%7},{%8,%9},{%0,%1,%2,%3};"
                 : "+f"(d[0]), "+f"(d[1]), "+f"(d[2]), "+f"(d[3])
                 : "r"(a[0]), "r"(a[1]), "r"(a[2]), "r"(a[3]), "r"(*b0), "r"(*b1));
}

// ============================================================
// 0) compaction of active (c,w) rows
// ============================================================
__global__ void prep_kernel(const int* __restrict__ cap_lens) {
    __shared__ int offs[C_ + 1];
    int tid = threadIdx.x;
    if (tid == 0) {
        int run = 0;
        for (int c = 0; c < C_; c++) { offs[c] = run; run += cap_lens[c]; }
        offs[C_] = run;
        d_act_total = run;
    }
    __syncthreads();
    int c = tid;
    int off = offs[c], nw = cap_lens[c];
    d_actoff[c] = off;
    for (int w = 0; w < nw; w++) d_rowmap[off + w] = c * W_ + w;
    int total = offs[C_];
    for (int idx = total + tid; idx < MROWS; idx += C_) d_rowmap[idx] = 0;
}

// ============================================================
// mega kernel: convert + gram + capn
// ============================================================
__device__ __forceinline__ void do_convert(int t, const float* __restrict__ caps,
                                           const float* __restrict__ imgs) {
    const float* src;
    size_t dsto;
    __nv_bfloat16 *bh, *bl;
    if (t < ACH) {
        int row = t >> 7, c8 = t & 127;
        src = caps + (size_t)d_rowmap[row] * D_ + c8 * 8;
        dsto = (size_t)row * D_ + c8 * 8;
        bh = d_Ath; bl = d_Atl;
    } else {
        int u = t - ACH;
        int row = u >> 7, c8 = u & 127;
        src = imgs + (size_t)row * D_ + c8 * 8;
        dsto = (size_t)row * D_ + c8 * 8;
        bh = d_Bth; bl = d_Btl;
    }
    float4 v0 = *reinterpret_cast<const float4*>(src);
    float4 v1 = *reinterpret_cast<const float4*>(src + 4);
    float v[8] = {v0.x, v0.y, v0.z, v0.w, v1.x, v1.y, v1.z, v1.w};
    union { __nv_bfloat16 h[8]; uint4 u; } Hi, Lo;
    #pragma unroll
    for (int k = 0; k < 8; k++) {
        __nv_bfloat16 hb = __float2bfloat16(v[k]);
        float r = v[k] - __bfloat162float(hb);
        Hi.h[k] = hb;
        Lo.h[k] = __float2bfloat16(r);
    }
    *reinterpret_cast<uint4*>(bh + dsto) = Hi.u;
    *reinterpret_cast<uint4*>(bl + dsto) = Lo.u;
}

__global__ void __launch_bounds__(256) mega_kernel(const float* __restrict__ caps,
                                                   const float* __restrict__ imgs) {
    __shared__ float sm[R_][132];
    int b = blockIdx.x, tid = threadIdx.x;

    if (b < CONVB) {
        do_convert(b * 256 + tid, caps, imgs);
        return;
    }
    if (b < CONVB + GRAMB) {
        int gb = b - CONVB;
        int i = gb >> 3, ch = gb & 7;
        const float* base = imgs + (size_t)i * R_ * D_ + ch * 128;
        for (int idx = tid; idx < R_ * 32; idx += 256) {
            int r = idx >> 5, d4 = idx & 31;
            float4 v = *reinterpret_cast<const float4*>(base + r * D_ + d4 * 4);
            *reinterpret_cast<float4*>(&sm[r][d4 * 4]) = v;
        }
        __syncthreads();
        if (tid < 144) {
            int tr = tid / 12, tc = tid % 12;
            float acc[3][3] = {};
            #pragma unroll 2
            for (int d = 0; d < 128; d += 4) {
                float4 A0 = *reinterpret_cast<const float4*>(&sm[tr*3+0][d]);
                float4 A1 = *reinterpret_cast<const float4*>(&sm[tr*3+1][d]);
                float4 A2 = *reinterpret_cast<const float4*>(&sm[tr*3+2][d]);
                float4 B0 = *reinterpret_cast<const float4*>(&sm[tc*3+0][d]);
                float4 B1 = *reinterpret_cast<const float4*>(&sm[tc*3+1][d]);
                float4 B2 = *reinterpret_cast<const float4*>(&sm[tc*3+2][d]);
                acc[0][0] = fmaf(A0.x,B0.x,fmaf(A0.y,B0.y,fmaf(A0.z,B0.z,fmaf(A0.w,B0.w,acc[0][0]))));
                acc[0][1] = fmaf(A0.x,B1.x,fmaf(A0.y,B1.y,fmaf(A0.z,B1.z,fmaf(A0.w,B1.w,acc[0][1]))));
                acc[0][2] = fmaf(A0.x,B2.x,fmaf(A0.y,B2.y,fmaf(A0.z,B2.z,fmaf(A0.w,B2.w,acc[0][2]))));
                acc[1][0] = fmaf(A1.x,B0.x,fmaf(A1.y,B0.y,fmaf(A1.z,B0.z,fmaf(A1.w,B0.w,acc[1][0]))));
                acc[1][1] = fmaf(A1.x,B1.x,fmaf(A1.y,B1.y,fmaf(A1.z,B1.z,fmaf(A1.w,B1.w,acc[1][1]))));
                acc[1][2] = fmaf(A1.x,B2.x,fmaf(A1.y,B2.y,fmaf(A1.z,B2.z,fmaf(A1.w,B2.w,acc[1][2]))));
                acc[2][0] = fmaf(A2.x,B0.x,fmaf(A2.y,B0.y,fmaf(A2.z,B0.z,fmaf(A2.w,B0.w,acc[2][0]))));
                acc[2][1] = fmaf(A2.x,B1.x,fmaf(A2.y,B1.y,fmaf(A2.z,B1.z,fmaf(A2.w,B1.w,acc[2][1]))));
                acc[2][2] = fmaf(A2.x,B2.x,fmaf(A2.y,B2.y,fmaf(A2.z,B2.z,fmaf(A2.w,B2.w,acc[2][2]))));
            }
            float* dst = d_Gp[ch] + i * (R_*R_);
            #pragma unroll
            for (int a = 0; a < 3; a++)
                #pragma unroll
                for (int bb = 0; bb < 3; bb++)
                    dst[(tr*3+a) * R_ + (tc*3+bb)] = acc[a][bb];
        }
        return;
    }
    // capn
    {
        int c = b - (CONVB + GRAMB);
        int w = tid >> 3, l = tid & 7;
        const float* p = caps + ((size_t)(c * W_ + w)) * D_;
        float s = 0.f;
        for (int d = l; d < D_; d += 8) { float v = p[d]; s += v * v; }
        s += __shfl_down_sync(0xffffffffu, s, 4);
        s += __shfl_down_sync(0xffffffffu, s, 2);
        s += __shfl_down_sync(0xffffffffu, s, 1);
        if (l == 0) d_capn[c * W_ + w] = s;
    }
}

// ============================================================
// HMMA bf16x3 GEMM (BM=64, 2 CTAs/SM) + fused gram reduce row
// ============================================================
__global__ void __launch_bounds__(256, 2) gemm_mma_kernel() {
    extern __shared__ __align__(128) char smc[];
    int tid = threadIdx.x;

    if (blockIdx.y == MB2) {
        for (int t = blockIdx.x * 256 + tid; t < GSZ; t += NB2 * 256) {
            float s = 0.f;
            #pragma unroll
            for (int p = 0; p < GCH; p++) s += d_Gp[p][t];
            d_G[t] = s;
        }
        return;
    }

    uint32_t sb = smem_u32(smc);
    int wid = tid >> 5, lane = tid & 31;

    int act = d_act_total;
    int mblk = blockIdx.y;
    if (mblk * BM >= act) return;
    int nblk = blockIdx.x;

    int wr = wid & 1, wc = wid >> 1;

    const __nv_bfloat16* srcA[2] = {
        d_Ath + (size_t)mblk * BM * D_,
        d_Atl + (size_t)mblk * BM * D_
    };
    const __nv_bfloat16* srcB[2] = {
        d_Bth + (size_t)nblk * BN * D_,
        d_Btl + (size_t)nblk * BN * D_
    };

    int q = lane >> 3, lr = lane & 7;
    int rowoff = ((q & 1) << 3) + lr;
    int csel = q >> 1;
    uint32_t aoff = (uint32_t)((wr * 32 + rowoff) * ROWB + csel * 16);
    uint32_t boff = (uint32_t)((wc * 32 + rowoff) * ROWB + csel * 16);

    float acc[2][4][4] = {};

    #define LOAD_STAGE(s, k0) do {                                              \
        _Pragma("unroll")                                                        \
        for (int it = 0; it < 6; it++) {                                         \
            int ci = tid + it * 256;                                             \
            const char* g; uint32_t dd;                                          \
            if (ci < 512) {                                                      \
                int tt = ci >> 8, r2 = ci & 255;                                  \
                int row = r2 >> 2, cc = r2 & 3;                                   \
                g = (const char*)(srcA[tt] + (size_t)row * D_ + (k0)) + cc * 16;  \
                dd = sb + (uint32_t)((s) * STGB + tt * TA + row * ROWB + cc * 16);\
            } else {                                                              \
                int u = ci - 512;                                                 \
                int tt = u >> 9, r2 = u & 511;                                    \
                int row = r2 >> 2, cc = r2 & 3;                                   \
                g = (const char*)(srcB[tt] + (size_t)row * D_ + (k0)) + cc * 16;  \
                dd = sb + (uint32_t)((s) * STGB + 2 * TA + tt * TB + row * ROWB + cc * 16); \
            }                                                                     \
            cpasync16(dd, g);                                                     \
        }                                                                         \
        CP_COMMIT();                                                              \
    } while (0)

    LOAD_STAGE(0, 0);

    for (int ks = 0; ks < NSTAGE; ks++) {
        int s = ks & 1;
        if (ks + 1 < NSTAGE) { LOAD_STAGE(s ^ 1, (ks + 1) * BK); CP_WAIT(1); }
        else                 { CP_WAIT(0); }
        __syncthreads();

        uint32_t bAh = sb + (uint32_t)(s * STGB);
        uint32_t bAl = bAh + TA;
        uint32_t bBh = bAh + 2 * TA;
        uint32_t bBl = bBh + TB;

        #pragma unroll
        for (int k16 = 0; k16 < 2; k16++) {
            uint32_t kb = (uint32_t)(k16 * 32);
            uint32_t ah[2][4], al[2][4];
            uint32_t bhf[4][2], blf[4][2];
            #pragma unroll
            for (int mt = 0; mt < 2; mt++) {
                ldsm4(ah[mt], bAh + (uint32_t)(mt * 16 * ROWB) + kb + aoff);
                ldsm4(al[mt], bAl + (uint32_t)(mt * 16 * ROWB) + kb + aoff);
            }
            #pragma unroll
            for (int np = 0; np < 2; np++) {
                uint32_t t4[4];
                ldsm4(t4, bBh + (uint32_t)(np * 16 * ROWB) + kb + boff);
                bhf[np*2+0][0] = t4[0]; bhf[np*2+0][1] = t4[2];
                bhf[np*2+1][0] = t4[1]; bhf[np*2+1][1] = t4[3];
                ldsm4(t4, bBl + (uint32_t)(np * 16 * ROWB) + kb + boff);
                blf[np*2+0][0] = t4[0]; blf[np*2+0][1] = t4[2];
                blf[np*2+1][0] = t4[1]; blf[np*2+1][1] = t4[3];
            }
            #pragma unroll
            for (int mt = 0; mt < 2; mt++)
                #pragma unroll
                for (int nt = 0; nt < 4; nt++) {
                    mma16816(acc[mt][nt], ah[mt], &bhf[nt][0], &bhf[nt][1]);
                    mma16816(acc[mt][nt], ah[mt], &blf[nt][0], &blf[nt][1]);
                    mma16816(acc[mt][nt], al[mt], &bhf[nt][0], &bhf[nt][1]);
                }
        }
        __syncthreads();
    }

    int g = lane >> 2, tq = lane & 3;
    #pragma unroll
    for (int mt = 0; mt < 2; mt++) {
        int m0 = mblk * BM + wr * 32 + mt * 16 + g;
        #pragma unroll
        for (int nt = 0; nt < 4; nt++) {
            int n = nblk * BN + wc * 32 + nt * 8 + tq * 2;
            if (m0 < act)
                *reinterpret_cast<float2*>(d_S + (size_t)m0 * N_ + n) =
                    make_float2(acc[mt][nt][0], acc[mt][nt][1]);
            if (m0 + 8 < act)
                *reinterpret_cast<float2*>(d_S + (size_t)(m0 + 8) * N_ + n) =
                    make_float2(acc[mt][nt][2], acc[mt][nt][3]);
        }
    }
}

// ============================================================
// epilogue per (c,i): smem two-phase p^T G p (no shfl broadcast loop)
// ============================================================
__global__ void __launch_bounds__(128) post_kernel(const int* __restrict__ cap_lens,
                                                   float* __restrict__ out) {
    int i = blockIdx.x, c = blockIdx.y;
    int tid = threadIdx.x;
    int lane = tid & 31, wid = tid >> 5;
    int nw = cap_lens[c], m0 = d_actoff[c];

    __shared__ float Ss[W_][37];
    __shared__ __align__(16) float Ps[W_][40];   // p, padded cols 36..39 zero
    __shared__ float Ys[W_][37];                 // Y = G p
    __shared__ __align__(16) float Gs[R_][44];   // stride 44: conflict-free f4
    __shared__ float cn[R_];
    __shared__ float dots[W_];

    if (tid < W_ && tid >= nw)
        out[((size_t)i * C_ + c) * W_ + tid] = MASK_VAL_;

    // load G (symmetric: Gs[x][y] = G[x*36+y]) + zero pads cols 36..39
    const float* gG = d_G + i * (R_ * R_);
    for (int idx = tid; idx < R_ * R_; idx += 128)
        Gs[idx / R_][idx % R_] = gG[idx];
    for (int idx = tid; idx < R_ * 4; idx += 128)
        Gs[idx >> 2][R_ + (idx & 3)] = 0.f;
    // load raw S rows
    for (int idx = tid; idx < nw * R_; idx += 128) {
        int w = idx / R_, r = idx - w * R_;
        Ss[w][r] = d_S[(size_t)(m0 + w) * N_ + i * R_ + r];
    }
    __syncthreads();

    // cn[r] = sqrt(sum_w leaky^2) + EPS
    if (tid < R_) {
        float s = 0.f;
        for (int w = 0; w < nw; w++) {
            float v = Ss[w][tid];
            v = (v >= 0.f) ? v : 0.1f * v;
            s += v * v;
        }
        cn[tid] = sqrtf(s) + EPS_;
    }
    __syncthreads();

    // phase 2: softmax per w (warp per w); write Ps (padded), dots
    for (int w = wid; w < nw; w += 4) {
        float s0 = Ss[w][lane];
        float s1 = (lane < 4) ? Ss[w][32 + lane] : 0.f;
        float l0 = (s0 >= 0.f) ? s0 : 0.1f * s0;
        float l1 = (s1 >= 0.f) ? s1 : 0.1f * s1;
        float a0 = l0 / cn[lane] * SMOOTH_;
        float a1 = (lane < 4) ? (l1 / cn[32 + lane] * SMOOTH_) : -1e30f;

        float mx = fmaxf(a0, a1);
        #pragma unroll
        for (int o = 16; o; o >>= 1) mx = fmaxf(mx, __shfl_xor_sync(~0u, mx, o));
        float e0 = expf(a0 - mx);
        float e1 = (lane < 4) ? expf(a1 - mx) : 0.f;
        float sum = e0 + e1;
        #pragma unroll
        for (int o = 16; o; o >>= 1) sum += __shfl_xor_sync(~0u, sum, o);
        float inv = 1.f / sum;
        float p0 = e0 * inv, p1 = e1 * inv;

        float dot = p0 * s0 + p1 * s1;
        #pragma unroll
        for (int o = 16; o; o >>= 1) dot += __shfl_xor_sync(~0u, dot, o);

        Ps[w][lane] = p0;
        if (lane < 4) Ps[w][32 + lane] = p1;
        else if (lane < 8) Ps[w][32 + lane] = 0.f;   // zero pads 36..39
        if (lane == 0) dots[w] = dot;
    }
    __syncthreads();

    // phase 3: Y[w][r2] = sum_r P[w][r] * G[r2][r]  (float4, Ps broadcast)
    int tot = nw * R_;
    for (int idx = tid; idx < tot; idx += 128) {
        int w = idx / R_, r2 = idx - w * R_;
        const float4* pp = reinterpret_cast<const float4*>(&Ps[w][0]);
        const float4* gg = reinterpret_cast<const float4*>(&Gs[r2][0]);
        float y = 0.f;
        #pragma unroll
        for (int j = 0; j < 10; j++) {
            float4 a = pp[j], b = gg[j];
            y = fmaf(a.x, b.x, y); y = fmaf(a.y, b.y, y);
            y = fmaf(a.z, b.z, y); y = fmaf(a.w, b.w, y);
        }
        Ys[w][r2] = y;
    }
    __syncthreads();

    // phase 4: q = p . Y ; finish sim
    for (int w = wid; w < nw; w += 4) {
        float v = Ps[w][lane] * Ys[w][lane];
        if (lane < 4) v = fmaf(Ps[w][32 + lane], Ys[w][32 + lane], v);
        #pragma unroll
        for (int o = 16; o; o >>= 1) v += __shfl_xor_sync(~0u, v, o);
        if (lane == 0) {
            float n = sqrtf(v);
            float denom = n + EPS_;
            float w12 = dots[w] / denom;
            float w2v = n / denom;
            float w1v = sqrtf(d_capn[c * W_ + w]);
            float sim = w12 / fmaxf(w1v * w2v, EPS_);
            out[((size_t)i * C_ + c) * W_ + w] = sim;
        }
    }
}

// ============================================================
extern "C" void kernel_launch(void* const* d_in, const int* in_sizes, int n_in,
                              void* d_out, int out_size) {
    const float* imgs     = (const float*)d_in[0];
    const float* caps     = (const float*)d_in[1];
    const int*   cap_lens = (const int*)d_in[3];
    float* out = (float*)d_out;

    cudaFuncSetAttribute(gemm_mma_kernel, cudaFuncAttributeMaxDynamicSharedMemorySize, GEMM_SMEM);

    prep_kernel<<<1, C_>>>(cap_lens);
    mega_kernel<<<MEGAB, 256>>>(caps, imgs);
    dim3 ggrid(NB2, MB2 + 1);   // (18, 33): last y-row = gram reduce
    gemm_mma_kernel<<<ggrid, 256, GEMM_SMEM>>>();
    dim3 pgrid(I_, C_);
    post_kernel<<<pgrid, 128>>>(cap_lens, out);
}

// round 8
// speedup vs baseline: 2.7947x; 1.1337x over previous
#include <cuda_runtime.h>
#include <cuda_bf16.h>
#include <cstdint>
#include <math.h>

#define I_ 64
#define R_ 36
#define D_ 1024
#define C_ 64
#define W_ 32
#define N_ (I_*R_)       // 2304
#define MROWS (C_*W_)    // 2048
#define SMOOTH_ 9.0f
#define EPS_ 1e-8f
#define MASK_VAL_ (-1.0f)

// GEMM tiling (BM=64 for wave balance)
#define BM 64
#define BN 128
#define BK 32
#define NSTAGE (D_/BK)           // 32
#define ROWB 80
#define TA (BM*ROWB)             // 5120
#define TB (BN*ROWB)             // 10240
#define STGB (2*TA + 2*TB)       // 30720
#define GEMM_SMEM (2*STGB)       // 61440
#define MB2 (MROWS/BM)           // 32
#define NB2 (N_/BN)              // 18

// Gram k-split
#define GCH 8
#define GSZ (I_*R_*R_)           // 82944

// mega-kernel partition
#define ACH (MROWS * (D_/8))     // 262144
#define BCH (N_ * (D_/8))        // 294912
#define CONVB ((ACH + BCH) / 256) // 2176
#define GRAMB (I_ * GCH)          // 512
#define CAPNB C_                  // 64
#define MEGAB (CONVB + GRAMB + CAPNB)

// ---- static scratch ----
__device__ float d_S[MROWS * N_];
__device__ float d_G[GSZ];
__device__ float d_Gp[GCH][GSZ];
__device__ float d_capn[C_ * W_];
__device__ int   d_rowmap[MROWS];
__device__ int   d_actoff[C_];
__device__ int   d_act_total;

__device__ __nv_bfloat16 d_Ath[MROWS * D_];
__device__ __nv_bfloat16 d_Atl[MROWS * D_];
__device__ __nv_bfloat16 d_Bth[N_ * D_];
__device__ __nv_bfloat16 d_Btl[N_ * D_];

// ================= PTX helpers =================
__device__ __forceinline__ uint32_t smem_u32(const void* p) {
    uint32_t a;
    asm("{ .reg .u64 t; cvta.to.shared.u64 t, %1; cvt.u32.u64 %0, t; }" : "=r"(a) : "l"(p));
    return a;
}
__device__ __forceinline__ void cpasync16(uint32_t dst, const void* src) {
    asm volatile("cp.async.cg.shared.global [%0], [%1], 16;" :: "r"(dst), "l"(src) : "memory");
}
#define CP_COMMIT() asm volatile("cp.async.commit_group;" ::: "memory")
#define CP_WAIT(n)  asm volatile("cp.async.wait_group %0;" :: "n"(n) : "memory")

__device__ __forceinline__ void ldsm4(uint32_t r[4], uint32_t addr) {
    asm volatile("ldmatrix.sync.aligned.m8n8.x4.shared.b16 {%0,%1,%2,%3}, [%4];"
                 : "=r"(r[0]), "=r"(r[1]), "=r"(r[2]), "=r"(r[3]) : "r"(addr));
}
__device__ __forceinline__ void mma16816(float* d, const uint32_t* a, const uint32_t* b0, const uint32_t* b1) {
    asm volatile("mma.sync.aligned.m16n8k16.row.col.f32.bf16.bf16.f32 "
                 "{%0,%1,%2,%3},{%4,%5,%6,%7},{%8,%9},{%0,%1,%2,%3};"
                 : "+f"(d[0]), "+f"(d[1]), "+f"(d[2]), "+f"(d[3])
                 : "r"(a[0]), "r"(a[1]), "r"(a[2]), "r"(a[3]), "r"(*b0), "r"(*b1));
}

// ============================================================
// 0) compaction of active (c,w) rows
// ============================================================
__global__ void prep_kernel(const int* __restrict__ cap_lens) {
    __shared__ int offs[C_ + 1];
    int tid = threadIdx.x;
    if (tid == 0) {
        int run = 0;
        for (int c = 0; c < C_; c++) { offs[c] = run; run += cap_lens[c]; }
        offs[C_] = run;
        d_act_total = run;
    }
    __syncthreads();
    int c = tid;
    int off = offs[c], nw = cap_lens[c];
    d_actoff[c] = off;
    for (int w = 0; w < nw; w++) d_rowmap[off + w] = c * W_ + w;
    int total = offs[C_];
    for (int idx = total + tid; idx < MROWS; idx += C_) d_rowmap[idx] = 0;
}

// ============================================================
// mega kernel: convert + gram + capn
// ============================================================
__device__ __forceinline__ void do_convert(int t, const float* __restrict__ caps,
                                           const float* __restrict__ imgs) {
    const float* src;
    size_t dsto;
    __nv_bfloat16 *bh, *bl;
    if (t < ACH) {
        int row = t >> 7, c8 = t & 127;
        src = caps + (size_t)d_rowmap[row] * D_ + c8 * 8;
        dsto = (size_t)row * D_ + c8 * 8;
        bh = d_Ath; bl = d_Atl;
    } else {
        int u = t - ACH;
        int row = u >> 7, c8 = u & 127;
        src = imgs + (size_t)row * D_ + c8 * 8;
        dsto = (size_t)row * D_ + c8 * 8;
        bh = d_Bth; bl = d_Btl;
    }
    float4 v0 = *reinterpret_cast<const float4*>(src);
    float4 v1 = *reinterpret_cast<const float4*>(src + 4);
    float v[8] = {v0.x, v0.y, v0.z, v0.w, v1.x, v1.y, v1.z, v1.w};
    union { __nv_bfloat16 h[8]; uint4 u; } Hi, Lo;
    #pragma unroll
    for (int k = 0; k < 8; k++) {
        __nv_bfloat16 hb = __float2bfloat16(v[k]);
        float r = v[k] - __bfloat162float(hb);
        Hi.h[k] = hb;
        Lo.h[k] = __float2bfloat16(r);
    }
    *reinterpret_cast<uint4*>(bh + dsto) = Hi.u;
    *reinterpret_cast<uint4*>(bl + dsto) = Lo.u;
}

__global__ void __launch_bounds__(256) mega_kernel(const float* __restrict__ caps,
                                                   const float* __restrict__ imgs) {
    __shared__ float sm[R_][132];
    int b = blockIdx.x, tid = threadIdx.x;

    if (b < CONVB) {
        do_convert(b * 256 + tid, caps, imgs);
        return;
    }
    if (b < CONVB + GRAMB) {
        int gb = b - CONVB;
        int i = gb >> 3, ch = gb & 7;
        const float* base = imgs + (size_t)i * R_ * D_ + ch * 128;
        for (int idx = tid; idx < R_ * 32; idx += 256) {
            int r = idx >> 5, d4 = idx & 31;
            float4 v = *reinterpret_cast<const float4*>(base + r * D_ + d4 * 4);
            *reinterpret_cast<float4*>(&sm[r][d4 * 4]) = v;
        }
        __syncthreads();
        if (tid < 144) {
            int tr = tid / 12, tc = tid % 12;
            float acc[3][3] = {};
            #pragma unroll 2
            for (int d = 0; d < 128; d += 4) {
                float4 A0 = *reinterpret_cast<const float4*>(&sm[tr*3+0][d]);
                float4 A1 = *reinterpret_cast<const float4*>(&sm[tr*3+1][d]);
                float4 A2 = *reinterpret_cast<const float4*>(&sm[tr*3+2][d]);
                float4 B0 = *reinterpret_cast<const float4*>(&sm[tc*3+0][d]);
                float4 B1 = *reinterpret_cast<const float4*>(&sm[tc*3+1][d]);
                float4 B2 = *reinterpret_cast<const float4*>(&sm[tc*3+2][d]);
                acc[0][0] = fmaf(A0.x,B0.x,fmaf(A0.y,B0.y,fmaf(A0.z,B0.z,fmaf(A0.w,B0.w,acc[0][0]))));
                acc[0][1] = fmaf(A0.x,B1.x,fmaf(A0.y,B1.y,fmaf(A0.z,B1.z,fmaf(A0.w,B1.w,acc[0][1]))));
                acc[0][2] = fmaf(A0.x,B2.x,fmaf(A0.y,B2.y,fmaf(A0.z,B2.z,fmaf(A0.w,B2.w,acc[0][2]))));
                acc[1][0] = fmaf(A1.x,B0.x,fmaf(A1.y,B0.y,fmaf(A1.z,B0.z,fmaf(A1.w,B0.w,acc[1][0]))));
                acc[1][1] = fmaf(A1.x,B1.x,fmaf(A1.y,B1.y,fmaf(A1.z,B1.z,fmaf(A1.w,B1.w,acc[1][1]))));
                acc[1][2] = fmaf(A1.x,B2.x,fmaf(A1.y,B2.y,fmaf(A1.z,B2.z,fmaf(A1.w,B2.w,acc[1][2]))));
                acc[2][0] = fmaf(A2.x,B0.x,fmaf(A2.y,B0.y,fmaf(A2.z,B0.z,fmaf(A2.w,B0.w,acc[2][0]))));
                acc[2][1] = fmaf(A2.x,B1.x,fmaf(A2.y,B1.y,fmaf(A2.z,B1.z,fmaf(A2.w,B1.w,acc[2][1]))));
                acc[2][2] = fmaf(A2.x,B2.x,fmaf(A2.y,B2.y,fmaf(A2.z,B2.z,fmaf(A2.w,B2.w,acc[2][2]))));
            }
            float* dst = d_Gp[ch] + i * (R_*R_);
            #pragma unroll
            for (int a = 0; a < 3; a++)
                #pragma unroll
                for (int bb = 0; bb < 3; bb++)
                    dst[(tr*3+a) * R_ + (tc*3+bb)] = acc[a][bb];
        }
        return;
    }
    // capn
    {
        int c = b - (CONVB + GRAMB);
        int w = tid >> 3, l = tid & 7;
        const float* p = caps + ((size_t)(c * W_ + w)) * D_;
        float s = 0.f;
        for (int d = l; d < D_; d += 8) { float v = p[d]; s += v * v; }
        s += __shfl_down_sync(0xffffffffu, s, 4);
        s += __shfl_down_sync(0xffffffffu, s, 2);
        s += __shfl_down_sync(0xffffffffu, s, 1);
        if (l == 0) d_capn[c * W_ + w] = s;
    }
}

// ============================================================
// HMMA bf16x3 GEMM (BM=64, 2 CTAs/SM) + fused gram reduce row
// ============================================================
__global__ void __launch_bounds__(256, 2) gemm_mma_kernel() {
    extern __shared__ __align__(128) char smc[];
    int tid = threadIdx.x;

    if (blockIdx.y == MB2) {
        for (int t = blockIdx.x * 256 + tid; t < GSZ; t += NB2 * 256) {
            float s = 0.f;
            #pragma unroll
            for (int p = 0; p < GCH; p++) s += d_Gp[p][t];
            d_G[t] = s;
        }
        return;
    }

    uint32_t sb = smem_u32(smc);
    int wid = tid >> 5, lane = tid & 31;

    int act = d_act_total;
    int mblk = blockIdx.y;
    if (mblk * BM >= act) return;
    int nblk = blockIdx.x;

    int wr = wid & 1, wc = wid >> 1;

    const __nv_bfloat16* srcA[2] = {
        d_Ath + (size_t)mblk * BM * D_,
        d_Atl + (size_t)mblk * BM * D_
    };
    const __nv_bfloat16* srcB[2] = {
        d_Bth + (size_t)nblk * BN * D_,
        d_Btl + (size_t)nblk * BN * D_
    };

    int q = lane >> 3, lr = lane & 7;
    int rowoff = ((q & 1) << 3) + lr;
    int csel = q >> 1;
    uint32_t aoff = (uint32_t)((wr * 32 + rowoff) * ROWB + csel * 16);
    uint32_t boff = (uint32_t)((wc * 32 + rowoff) * ROWB + csel * 16);

    float acc[2][4][4] = {};

    #define LOAD_STAGE(s, k0) do {                                              \
        _Pragma("unroll")                                                        \
        for (int it = 0; it < 6; it++) {                                         \
            int ci = tid + it * 256;                                             \
            const char* g; uint32_t dd;                                          \
            if (ci < 512) {                                                      \
                int tt = ci >> 8, r2 = ci & 255;                                  \
                int row = r2 >> 2, cc = r2 & 3;                                   \
                g = (const char*)(srcA[tt] + (size_t)row * D_ + (k0)) + cc * 16;  \
                dd = sb + (uint32_t)((s) * STGB + tt * TA + row * ROWB + cc * 16);\
            } else {                                                              \
                int u = ci - 512;                                                 \
                int tt = u >> 9, r2 = u & 511;                                    \
                int row = r2 >> 2, cc = r2 & 3;                                   \
                g = (const char*)(srcB[tt] + (size_t)row * D_ + (k0)) + cc * 16;  \
                dd = sb + (uint32_t)((s) * STGB + 2 * TA + tt * TB + row * ROWB + cc * 16); \
            }                                                                     \
            cpasync16(dd, g);                                                     \
        }                                                                         \
        CP_COMMIT();                                                              \
    } while (0)

    LOAD_STAGE(0, 0);

    for (int ks = 0; ks < NSTAGE; ks++) {
        int s = ks & 1;
        if (ks + 1 < NSTAGE) { LOAD_STAGE(s ^ 1, (ks + 1) * BK); CP_WAIT(1); }
        else                 { CP_WAIT(0); }
        __syncthreads();

        uint32_t bAh = sb + (uint32_t)(s * STGB);
        uint32_t bAl = bAh + TA;
        uint32_t bBh = bAh + 2 * TA;
        uint32_t bBl = bBh + TB;

        #pragma unroll
        for (int k16 = 0; k16 < 2; k16++) {
            uint32_t kb = (uint32_t)(k16 * 32);
            uint32_t ah[2][4], al[2][4];
            uint32_t bhf[4][2], blf[4][2];
            #pragma unroll
            for (int mt = 0; mt < 2; mt++) {
                ldsm4(ah[mt], bAh + (uint32_t)(mt * 16 * ROWB) + kb + aoff);
                ldsm4(al[mt], bAl + (uint32_t)(mt * 16 * ROWB) + kb + aoff);
            }
            #pragma unroll
            for (int np = 0; np < 2; np++) {
                uint32_t t4[4];
                ldsm4(t4, bBh + (uint32_t)(np * 16 * ROWB) + kb + boff);
                bhf[np*2+0][0] = t4[0]; bhf[np*2+0][1] = t4[2];
                bhf[np*2+1][0] = t4[1]; bhf[np*2+1][1] = t4[3];
                ldsm4(t4, bBl + (uint32_t)(np * 16 * ROWB) + kb + boff);
                blf[np*2+0][0] = t4[0]; blf[np*2+0][1] = t4[2];
                blf[np*2+1][0] = t4[1]; blf[np*2+1][1] = t4[3];
            }
            #pragma unroll
            for (int mt = 0; mt < 2; mt++)
                #pragma unroll
                for (int nt = 0; nt < 4; nt++) {
                    mma16816(acc[mt][nt], ah[mt], &bhf[nt][0], &bhf[nt][1]);
                    mma16816(acc[mt][nt], ah[mt], &blf[nt][0], &blf[nt][1]);
                    mma16816(acc[mt][nt], al[mt], &bhf[nt][0], &bhf[nt][1]);
                }
        }
        __syncthreads();
    }

    int g = lane >> 2, tq = lane & 3;
    #pragma unroll
    for (int mt = 0; mt < 2; mt++) {
        int m0 = mblk * BM + wr * 32 + mt * 16 + g;
        #pragma unroll
        for (int nt = 0; nt < 4; nt++) {
            int n = nblk * BN + wc * 32 + nt * 8 + tq * 2;
            if (m0 < act)
                *reinterpret_cast<float2*>(d_S + (size_t)m0 * N_ + n) =
                    make_float2(acc[mt][nt][0], acc[mt][nt][1]);
            if (m0 + 8 < act)
                *reinterpret_cast<float2*>(d_S + (size_t)(m0 + 8) * N_ + n) =
                    make_float2(acc[mt][nt][2], acc[mt][nt][3]);
        }
    }
}

// ============================================================
// epilogue: one warp per (c,i), one lane per w; p in registers,
// G rows read as float4 smem broadcasts.
// grid = (I_, C_/8), 256 threads
// ============================================================
__global__ void __launch_bounds__(256) post_kernel(const int* __restrict__ cap_lens,
                                                   float* __restrict__ out) {
    int i = blockIdx.x, cg = blockIdx.y;
    int tid = threadIdx.x, wid = tid >> 5, lane = tid & 31;
    int c = cg * 8 + wid;

    __shared__ float Gs[R_][R_];          // 36x36, row = 144B (16B aligned)
    __shared__ float Ss[8][W_][37];       // per-warp raw S staging
    __shared__ float cns[8][R_];

    // cooperative G load (once per 8 c's)
    const float* gG = d_G + i * (R_ * R_);
    for (int idx = tid; idx < R_ * R_; idx += 256)
        Gs[idx / R_][idx % R_] = gG[idx];

    int nw = cap_lens[c], m0 = d_actoff[c];

    // stage this warp's raw S rows: Ss[wid][w][r]
    for (int idx = lane; idx < nw * R_; idx += 32) {
        int w = idx / R_, r = idx - w * R_;
        Ss[wid][w][r] = d_S[(size_t)(m0 + w) * N_ + i * R_ + r];
    }
    __syncwarp();

    // cn[r] = sqrt(sum_w leaky(S)^2) + EPS   (lane r; lanes 0..3 also do r+32)
    {
        float s1 = 0.f, s2 = 0.f;
        for (int w = 0; w < nw; w++) {
            float v = Ss[wid][w][lane];
            v = (v >= 0.f) ? v : 0.1f * v;
            s1 = fmaf(v, v, s1);
            if (lane < 4) {
                float u = Ss[wid][w][32 + lane];
                u = (u >= 0.f) ? u : 0.1f * u;
                s2 = fmaf(u, u, s2);
            }
        }
        cns[wid][lane] = sqrtf(s1) + EPS_;
        if (lane < 4) cns[wid][32 + lane] = sqrtf(s2) + EPS_;
    }
    __syncthreads();   // Gs ready for everyone; cns ready per warp

    int w = lane;
    float sim = MASK_VAL_;
    if (w < nw) {
        float s[R_], a[R_];
        float mx = -1e30f;
        #pragma unroll
        for (int r = 0; r < R_; r++) {
            float v = Ss[wid][w][r];              // (5*lane + r) mod 32: conflict-free
            s[r] = v;
            float l = (v >= 0.f) ? v : 0.1f * v;
            float t = l / cns[wid][r] * SMOOTH_;  // broadcast LDS
            a[r] = t;
            mx = fmaxf(mx, t);
        }
        float sum = 0.f;
        #pragma unroll
        for (int r = 0; r < R_; r++) { float e = expf(a[r] - mx); a[r] = e; sum += e; }
        float inv = 1.f / sum;
        float dot = 0.f;
        #pragma unroll
        for (int r = 0; r < R_; r++) { a[r] *= inv; dot = fmaf(a[r], s[r], dot); }

        // q = p^T G p : per r, G row via float4 broadcast
        float q = 0.f;
        #pragma unroll
        for (int r = 0; r < R_; r++) {
            const float4* gr = reinterpret_cast<const float4*>(&Gs[r][0]);
            float y = 0.f;
            #pragma unroll
            for (int j = 0; j < 9; j++) {
                float4 g4 = gr[j];
                y = fmaf(g4.x, a[4*j+0], y);
                y = fmaf(g4.y, a[4*j+1], y);
                y = fmaf(g4.z, a[4*j+2], y);
                y = fmaf(g4.w, a[4*j+3], y);
            }
            q = fmaf(a[r], y, q);
        }

        float n = sqrtf(q);
        float denom = n + EPS_;
        float w12 = dot / denom;
        float w2v = n / denom;
        float w1v = sqrtf(d_capn[c * W_ + w]);
        sim = w12 / fmaxf(w1v * w2v, EPS_);
    }
    out[((size_t)i * C_ + c) * W_ + w] = sim;
}

// ============================================================
extern "C" void kernel_launch(void* const* d_in, const int* in_sizes, int n_in,
                              void* d_out, int out_size) {
    const float* imgs     = (const float*)d_in[0];
    const float* caps     = (const float*)d_in[1];
    const int*   cap_lens = (const int*)d_in[3];
    float* out = (float*)d_out;

    cudaFuncSetAttribute(gemm_mma_kernel, cudaFuncAttributeMaxDynamicSharedMemorySize, GEMM_SMEM);

    prep_kernel<<<1, C_>>>(cap_lens);
    mega_kernel<<<MEGAB, 256>>>(caps, imgs);
    dim3 ggrid(NB2, MB2 + 1);   // (18, 33): last y-row = gram reduce
    gemm_mma_kernel<<<ggrid, 256, GEMM_SMEM>>>();
    dim3 pgrid(I_, C_ / 8);
    post_kernel<<<pgrid, 256>>>(cap_lens, out);
}

// round 9
// speedup vs baseline: 2.9247x; 1.0465x over previous
#include <cuda_runtime.h>
#include <cuda_bf16.h>
#include <cstdint>
#include <math.h>

#define I_ 64
#define R_ 36
#define D_ 1024
#define C_ 64
#define W_ 32
#define N_ (I_*R_)       // 2304
#define MROWS (C_*W_)    // 2048
#define SMOOTH_ 9.0f
#define EPS_ 1e-8f
#define MASK_VAL_ (-1.0f)

// GEMM tiling (BM=64 for wave balance)
#define BM 64
#define BN 128
#define BK 32
#define NSTAGE (D_/BK)           // 32
#define ROWB 80
#define TA (BM*ROWB)             // 5120
#define TB (BN*ROWB)             // 10240
#define STGB (2*TA + 2*TB)       // 30720
#define GEMM_SMEM (2*STGB)       // 61440
#define MB2 (MROWS/BM)           // 32
#define NB2 (N_/BN)              // 18

// Gram k-split
#define GCH 8
#define GSZ (I_*R_*R_)           // 82944

// mega-kernel partition
#define ACH (MROWS * (D_/8))     // 262144
#define BCH (N_ * (D_/8))        // 294912
#define CONVB ((ACH + BCH) / 256) // 2176
#define GRAMB (I_ * GCH)          // 512
#define CAPNB C_                  // 64
#define MEGAB (CONVB + GRAMB + CAPNB)

// ---- static scratch ----
__device__ float d_S[MROWS * N_];
__device__ float d_G[GSZ];
__device__ float d_Gp[GCH][GSZ];
__device__ float d_capn[C_ * W_];
__device__ int   d_rowmap[MROWS];
__device__ int   d_actoff[C_];
__device__ int   d_act_total;

__device__ __nv_bfloat16 d_Ath[MROWS * D_];
__device__ __nv_bfloat16 d_Atl[MROWS * D_];
__device__ __nv_bfloat16 d_Bth[N_ * D_];
__device__ __nv_bfloat16 d_Btl[N_ * D_];

// ================= PTX helpers =================
__device__ __forceinline__ uint32_t smem_u32(const void* p) {
    uint32_t a;
    asm("{ .reg .u64 t; cvta.to.shared.u64 t, %1; cvt.u32.u64 %0, t; }" : "=r"(a) : "l"(p));
    return a;
}
__device__ __forceinline__ void cpasync16(uint32_t dst, const void* src) {
    asm volatile("cp.async.cg.shared.global [%0], [%1], 16;" :: "r"(dst), "l"(src) : "memory");
}
#define CP_COMMIT() asm volatile("cp.async.commit_group;" ::: "memory")
#define CP_WAIT(n)  asm volatile("cp.async.wait_group %0;" :: "n"(n) : "memory")

__device__ __forceinline__ void ldsm4(uint32_t r[4], uint32_t addr) {
    asm volatile("ldmatrix.sync.aligned.m8n8.x4.shared.b16 {%0,%1,%2,%3}, [%4];"
                 : "=r"(r[0]), "=r"(r[1]), "=r"(r[2]), "=r"(r[3]) : "r"(addr));
}
__device__ __forceinline__ void mma16816(float* d, const uint32_t* a, const uint32_t* b0, const uint32_t* b1) {
    asm volatile("mma.sync.aligned.m16n8k16.row.col.f32.bf16.bf16.f32 "
                 "{%0,%1,%2,%3},{%4,%5,%6,%7},{%8,%9},{%0,%1,%2,%3};"
                 : "+f"(d[0]), "+f"(d[1]), "+f"(d[2]), "+f"(d[3])
                 : "r"(a[0]), "r"(a[1]), "r"(a[2]), "r"(a[3]), "r"(*b0), "r"(*b1));
}

// ============================================================
// 0) compaction of active (c,w) rows
// ============================================================
__global__ void prep_kernel(const int* __restrict__ cap_lens) {
    __shared__ int offs[C_ + 1];
    int tid = threadIdx.x;
    if (tid == 0) {
        int run = 0;
        for (int c = 0; c < C_; c++) { offs[c] = run; run += cap_lens[c]; }
        offs[C_] = run;
        d_act_total = run;
    }
    __syncthreads();
    int c = tid;
    int off = offs[c], nw = cap_lens[c];
    d_actoff[c] = off;
    for (int w = 0; w < nw; w++) d_rowmap[off + w] = c * W_ + w;
    int total = offs[C_];
    for (int idx = total + tid; idx < MROWS; idx += C_) d_rowmap[idx] = 0;
}

// ============================================================
// mega kernel: convert + gram + capn
// ============================================================
__device__ __forceinline__ void do_convert(int t, const float* __restrict__ caps,
                                           const float* __restrict__ imgs) {
    const float* src;
    size_t dsto;
    __nv_bfloat16 *bh, *bl;
    if (t < ACH) {
        int row = t >> 7, c8 = t & 127;
        src = caps + (size_t)d_rowmap[row] * D_ + c8 * 8;
        dsto = (size_t)row * D_ + c8 * 8;
        bh = d_Ath; bl = d_Atl;
    } else {
        int u = t - ACH;
        int row = u >> 7, c8 = u & 127;
        src = imgs + (size_t)row * D_ + c8 * 8;
        dsto = (size_t)row * D_ + c8 * 8;
        bh = d_Bth; bl = d_Btl;
    }
    float4 v0 = *reinterpret_cast<const float4*>(src);
    float4 v1 = *reinterpret_cast<const float4*>(src + 4);
    float v[8] = {v0.x, v0.y, v0.z, v0.w, v1.x, v1.y, v1.z, v1.w};
    union { __nv_bfloat16 h[8]; uint4 u; } Hi, Lo;
    #pragma unroll
    for (int k = 0; k < 8; k++) {
        __nv_bfloat16 hb = __float2bfloat16(v[k]);
        float r = v[k] - __bfloat162float(hb);
        Hi.h[k] = hb;
        Lo.h[k] = __float2bfloat16(r);
    }
    *reinterpret_cast<uint4*>(bh + dsto) = Hi.u;
    *reinterpret_cast<uint4*>(bl + dsto) = Lo.u;
}

__global__ void __launch_bounds__(256) mega_kernel(const float* __restrict__ caps,
                                                   const float* __restrict__ imgs) {
    __shared__ float sm[R_][132];
    int b = blockIdx.x, tid = threadIdx.x;

    if (b < CONVB) {
        do_convert(b * 256 + tid, caps, imgs);
        return;
    }
    if (b < CONVB + GRAMB) {
        int gb = b - CONVB;
        int i = gb >> 3, ch = gb & 7;
        const float* base = imgs + (size_t)i * R_ * D_ + ch * 128;
        for (int idx = tid; idx < R_ * 32; idx += 256) {
            int r = idx >> 5, d4 = idx & 31;
            float4 v = *reinterpret_cast<const float4*>(base + r * D_ + d4 * 4);
            *reinterpret_cast<float4*>(&sm[r][d4 * 4]) = v;
        }
        __syncthreads();
        if (tid < 144) {
            int tr = tid / 12, tc = tid % 12;
            float acc[3][3] = {};
            #pragma unroll 2
            for (int d = 0; d < 128; d += 4) {
                float4 A0 = *reinterpret_cast<const float4*>(&sm[tr*3+0][d]);
                float4 A1 = *reinterpret_cast<const float4*>(&sm[tr*3+1][d]);
                float4 A2 = *reinterpret_cast<const float4*>(&sm[tr*3+2][d]);
                float4 B0 = *reinterpret_cast<const float4*>(&sm[tc*3+0][d]);
                float4 B1 = *reinterpret_cast<const float4*>(&sm[tc*3+1][d]);
                float4 B2 = *reinterpret_cast<const float4*>(&sm[tc*3+2][d]);
                acc[0][0] = fmaf(A0.x,B0.x,fmaf(A0.y,B0.y,fmaf(A0.z,B0.z,fmaf(A0.w,B0.w,acc[0][0]))));
                acc[0][1] = fmaf(A0.x,B1.x,fmaf(A0.y,B1.y,fmaf(A0.z,B1.z,fmaf(A0.w,B1.w,acc[0][1]))));
                acc[0][2] = fmaf(A0.x,B2.x,fmaf(A0.y,B2.y,fmaf(A0.z,B2.z,fmaf(A0.w,B2.w,acc[0][2]))));
                acc[1][0] = fmaf(A1.x,B0.x,fmaf(A1.y,B0.y,fmaf(A1.z,B0.z,fmaf(A1.w,B0.w,acc[1][0]))));
                acc[1][1] = fmaf(A1.x,B1.x,fmaf(A1.y,B1.y,fmaf(A1.z,B1.z,fmaf(A1.w,B1.w,acc[1][1]))));
                acc[1][2] = fmaf(A1.x,B2.x,fmaf(A1.y,B2.y,fmaf(A1.z,B2.z,fmaf(A1.w,B2.w,acc[1][2]))));
                acc[2][0] = fmaf(A2.x,B0.x,fmaf(A2.y,B0.y,fmaf(A2.z,B0.z,fmaf(A2.w,B0.w,acc[2][0]))));
                acc[2][1] = fmaf(A2.x,B1.x,fmaf(A2.y,B1.y,fmaf(A2.z,B1.z,fmaf(A2.w,B1.w,acc[2][1]))));
                acc[2][2] = fmaf(A2.x,B2.x,fmaf(A2.y,B2.y,fmaf(A2.z,B2.z,fmaf(A2.w,B2.w,acc[2][2]))));
            }
            float* dst = d_Gp[ch] + i * (R_*R_);
            #pragma unroll
            for (int a = 0; a < 3; a++)
                #pragma unroll
                for (int bb = 0; bb < 3; bb++)
                    dst[(tr*3+a) * R_ + (tc*3+bb)] = acc[a][bb];
        }
        return;
    }
    // capn
    {
        int c = b - (CONVB + GRAMB);
        int w = tid >> 3, l = tid & 7;
        const float* p = caps + ((size_t)(c * W_ + w)) * D_;
        float s = 0.f;
        for (int d = l; d < D_; d += 8) { float v = p[d]; s += v * v; }
        s += __shfl_down_sync(0xffffffffu, s, 4);
        s += __shfl_down_sync(0xffffffffu, s, 2);
        s += __shfl_down_sync(0xffffffffu, s, 1);
        if (l == 0) d_capn[c * W_ + w] = s;
    }
}

// ============================================================
// HMMA bf16x3 GEMM (BM=64, 2 CTAs/SM) + fused gram reduce row
// ============================================================
__global__ void __launch_bounds__(256, 2) gemm_mma_kernel() {
    extern __shared__ __align__(128) char smc[];
    int tid = threadIdx.x;

    if (blockIdx.y == MB2) {
        for (int t = blockIdx.x * 256 + tid; t < GSZ; t += NB2 * 256) {
            float s = 0.f;
            #pragma unroll
            for (int p = 0; p < GCH; p++) s += d_Gp[p][t];
            d_G[t] = s;
        }
        return;
    }

    uint32_t sb = smem_u32(smc);
    int wid = tid >> 5, lane = tid & 31;

    int act = d_act_total;
    int mblk = blockIdx.y;
    if (mblk * BM >= act) return;
    int nblk = blockIdx.x;

    int wr = wid & 1, wc = wid >> 1;

    const __nv_bfloat16* srcA[2] = {
        d_Ath + (size_t)mblk * BM * D_,
        d_Atl + (size_t)mblk * BM * D_
    };
    const __nv_bfloat16* srcB[2] = {
        d_Bth + (size_t)nblk * BN * D_,
        d_Btl + (size_t)nblk * BN * D_
    };

    int q = lane >> 3, lr = lane & 7;
    int rowoff = ((q & 1) << 3) + lr;
    int csel = q >> 1;
    uint32_t aoff = (uint32_t)((wr * 32 + rowoff) * ROWB + csel * 16);
    uint32_t boff = (uint32_t)((wc * 32 + rowoff) * ROWB + csel * 16);

    float acc[2][4][4] = {};

    #define LOAD_STAGE(s, k0) do {                                              \
        _Pragma("unroll")                                                        \
        for (int it = 0; it < 6; it++) {                                         \
            int ci = tid + it * 256;                                             \
            const char* g; uint32_t dd;                                          \
            if (ci < 512) {                                                      \
                int tt = ci >> 8, r2 = ci & 255;                                  \
                int row = r2 >> 2, cc = r2 & 3;                                   \
                g = (const char*)(srcA[tt] + (size_t)row * D_ + (k0)) + cc * 16;  \
                dd = sb + (uint32_t)((s) * STGB + tt * TA + row * ROWB + cc * 16);\
            } else {                                                              \
                int u = ci - 512;                                                 \
                int tt = u >> 9, r2 = u & 511;                                    \
                int row = r2 >> 2, cc = r2 & 3;                                   \
                g = (const char*)(srcB[tt] + (size_t)row * D_ + (k0)) + cc * 16;  \
                dd = sb + (uint32_t)((s) * STGB + 2 * TA + tt * TB + row * ROWB + cc * 16); \
            }                                                                     \
            cpasync16(dd, g);                                                     \
        }                                                                         \
        CP_COMMIT();                                                              \
    } while (0)

    LOAD_STAGE(0, 0);

    for (int ks = 0; ks < NSTAGE; ks++) {
        int s = ks & 1;
        if (ks + 1 < NSTAGE) { LOAD_STAGE(s ^ 1, (ks + 1) * BK); CP_WAIT(1); }
        else                 { CP_WAIT(0); }
        __syncthreads();

        uint32_t bAh = sb + (uint32_t)(s * STGB);
        uint32_t bAl = bAh + TA;
        uint32_t bBh = bAh + 2 * TA;
        uint32_t bBl = bBh + TB;

        #pragma unroll
        for (int k16 = 0; k16 < 2; k16++) {
            uint32_t kb = (uint32_t)(k16 * 32);
            uint32_t ah[2][4], al[2][4];
            uint32_t bhf[4][2], blf[4][2];
            #pragma unroll
            for (int mt = 0; mt < 2; mt++) {
                ldsm4(ah[mt], bAh + (uint32_t)(mt * 16 * ROWB) + kb + aoff);
                ldsm4(al[mt], bAl + (uint32_t)(mt * 16 * ROWB) + kb + aoff);
            }
            #pragma unroll
            for (int np = 0; np < 2; np++) {
                uint32_t t4[4];
                ldsm4(t4, bBh + (uint32_t)(np * 16 * ROWB) + kb + boff);
                bhf[np*2+0][0] = t4[0]; bhf[np*2+0][1] = t4[2];
                bhf[np*2+1][0] = t4[1]; bhf[np*2+1][1] = t4[3];
                ldsm4(t4, bBl + (uint32_t)(np * 16 * ROWB) + kb + boff);
                blf[np*2+0][0] = t4[0]; blf[np*2+0][1] = t4[2];
                blf[np*2+1][0] = t4[1]; blf[np*2+1][1] = t4[3];
            }
            #pragma unroll
            for (int mt = 0; mt < 2; mt++)
                #pragma unroll
                for (int nt = 0; nt < 4; nt++) {
                    mma16816(acc[mt][nt], ah[mt], &bhf[nt][0], &bhf[nt][1]);
                    mma16816(acc[mt][nt], ah[mt], &blf[nt][0], &blf[nt][1]);
                    mma16816(acc[mt][nt], al[mt], &bhf[nt][0], &bhf[nt][1]);
                }
        }
        __syncthreads();
    }

    int g = lane >> 2, tq = lane & 3;
    #pragma unroll
    for (int mt = 0; mt < 2; mt++) {
        int m0 = mblk * BM + wr * 32 + mt * 16 + g;
        #pragma unroll
        for (int nt = 0; nt < 4; nt++) {
            int n = nblk * BN + wc * 32 + nt * 8 + tq * 2;
            if (m0 < act)
                *reinterpret_cast<float2*>(d_S + (size_t)m0 * N_ + n) =
                    make_float2(acc[mt][nt][0], acc[mt][nt][1]);
            if (m0 + 8 < act)
                *reinterpret_cast<float2*>(d_S + (size_t)(m0 + 8) * N_ + n) =
                    make_float2(acc[mt][nt][2], acc[mt][nt][3]);
        }
    }
}

// ============================================================
// epilogue: one warp per (c,i), one lane per w; e (unnormalized
// softmax) in registers; q/dot rescaled by inv at the end.
// grid = (I_, C_/8), 256 threads
// ============================================================
__global__ void __launch_bounds__(256, 3) post_kernel(const int* __restrict__ cap_lens,
                                                      float* __restrict__ out) {
    int i = blockIdx.x, cg = blockIdx.y;
    int tid = threadIdx.x, wid = tid >> 5, lane = tid & 31;
    int c = cg * 8 + wid;

    __shared__ float Gs[R_][R_];          // 36x36, row = 144B
    __shared__ float Ss[8][W_][37];       // per-warp raw S staging
    __shared__ float rcn[8][R_];          // SMOOTH / (sqrt(.)+EPS)

    // cooperative G load (once per 8 c's)
    const float* gG = d_G + i * (R_ * R_);
    for (int idx = tid; idx < R_ * R_; idx += 256)
        Gs[idx / R_][idx % R_] = gG[idx];

    int nw = cap_lens[c], m0 = d_actoff[c];

    // stage this warp's raw S rows: Ss[wid][w][r]
    for (int idx = lane; idx < nw * R_; idx += 32) {
        int w = idx / R_, r = idx - w * R_;
        Ss[wid][w][r] = d_S[(size_t)(m0 + w) * N_ + i * R_ + r];
    }
    __syncwarp();

    // rcn[r] = SMOOTH / (sqrt(sum_w leaky^2) + EPS)   (lane r; lanes 0..3 also r+32)
    {
        float s1 = 0.f, s2 = 0.f;
        for (int w = 0; w < nw; w++) {
            float v = Ss[wid][w][lane];
            v = (v >= 0.f) ? v : 0.1f * v;
            s1 = fmaf(v, v, s1);
            if (lane < 4) {
                float u = Ss[wid][w][32 + lane];
                u = (u >= 0.f) ? u : 0.1f * u;
                s2 = fmaf(u, u, s2);
            }
        }
        rcn[wid][lane] = SMOOTH_ / (sqrtf(s1) + EPS_);
        if (lane < 4) rcn[wid][32 + lane] = SMOOTH_ / (sqrtf(s2) + EPS_);
    }
    __syncthreads();   // Gs ready for everyone; rcn ready per warp

    int w = lane;
    float sim = MASK_VAL_;
    if (w < nw) {
        float a[R_];
        float mx = -1e30f;
        #pragma unroll
        for (int r = 0; r < R_; r++) {
            float v = Ss[wid][w][r];              // conflict-free (stride 37)
            float l = (v >= 0.f) ? v : 0.1f * v;
            float t = l * rcn[wid][r];            // broadcast LDS + FMA
            a[r] = t;
            mx = fmaxf(mx, t);
        }
        float sum = 0.f, sd = 0.f;
        #pragma unroll
        for (int r = 0; r < R_; r++) {
            float e = __expf(a[r] - mx);
            a[r] = e;
            sum += e;
            sd = fmaf(e, Ss[wid][w][r], sd);      // e . s_raw (unnormalized)
        }
        float inv = 1.f / sum;

        // q_e = e^T G e : per r, G row via float4 broadcast
        float qe = 0.f;
        #pragma unroll
        for (int r = 0; r < R_; r++) {
            const float4* gr = reinterpret_cast<const float4*>(&Gs[r][0]);
            float y = 0.f;
            #pragma unroll
            for (int j = 0; j < 9; j++) {
                float4 g4 = gr[j];
                y = fmaf(g4.x, a[4*j+0], y);
                y = fmaf(g4.y, a[4*j+1], y);
                y = fmaf(g4.z, a[4*j+2], y);
                y = fmaf(g4.w, a[4*j+3], y);
            }
            qe = fmaf(a[r], y, qe);
        }

        float n = sqrtf(qe) * inv;                // ||wctx||
        float dot = sd * inv;                     // cap . wctx
        float denom = n + EPS_;
        float w12 = dot / denom;
        float w2v = n / denom;
        float w1v = sqrtf(d_capn[c * W_ + w]);
        sim = w12 / fmaxf(w1v * w2v, EPS_);
    }
    out[((size_t)i * C_ + c) * W_ + w] = sim;
}

// ============================================================
extern "C" void kernel_launch(void* const* d_in, const int* in_sizes, int n_in,
                              void* d_out, int out_size) {
    const float* imgs     = (const float*)d_in[0];
    const float* caps     = (const float*)d_in[1];
    const int*   cap_lens = (const int*)d_in[3];
    float* out = (float*)d_out;

    cudaFuncSetAttribute(gemm_mma_kernel, cudaFuncAttributeMaxDynamicSharedMemorySize, GEMM_SMEM);

    prep_kernel<<<1, C_>>>(cap_lens);
    mega_kernel<<<MEGAB, 256>>>(caps, imgs);
    dim3 ggrid(NB2, MB2 + 1);   // (18, 33): last y-row = gram reduce
    gemm_mma_kernel<<<ggrid, 256, GEMM_SMEM>>>();
    dim3 pgrid(I_, C_ / 8);
    post_kernel<<<pgrid, 256>>>(cap_lens, out);
}